// round 10
// baseline (speedup 1.0000x reference)
#include <cuda_runtime.h>
#include <cuda_bf16.h>
#include <math.h>
#include <stdint.h>

#define BSZ   32768
#define OBS   1024
#define OUTD  256
#define KCB   512
#define LOG2PI_F 1.83787706640934534f

// ---------------- fp32 scratch ---------------------------------------------------
__device__ float g_cbT[OBS * KCB];
__device__ float g_cnorm[KCB];
__device__ float g_xnorm[BSZ];
__device__ float g_h1[(size_t)BSZ * 512];
__device__ float g_h2[(size_t)BSZ * 1024];
__device__ float g_enc[(size_t)BSZ * 1024];
__device__ float g_dist[(size_t)BSZ * 512];
__device__ int   g_prop[BSZ];
__device__ float g_mu[(size_t)BSZ * 256];
__device__ float g_part[2048 * 2];
__device__ float g_total[1];
__device__ float g_zb[2048];                       // never written: stays zero
__device__ float g_z[(size_t)BSZ * 2048];          // z = X @ W1x (all columns, fp32)
__device__ float g_M2[1024 * 2048];                // cb^T @ W1d

// decoder computed on the 512 unique codebook rows only
__device__ float g_cb_d0[(size_t)KCB * 1024];
__device__ float g_cb_d1[(size_t)KCB * 2048];
__device__ float g_cb_d2[(size_t)KCB * 2048];
__device__ float g_cb_recon[(size_t)KCB * 1024];

// ---------------- saturation-analysis state ---------------------------------------
__device__ float g_colU[2048];     // u_j = sum_k W1d[k][j]
__device__ float g_colC[2048];     // c_j = cnorm @ W1d col j
__device__ float g_sj[2048];       // sign(u_j)
__device__ float g_m2n[2048];      // 2*||M2 col j||
__device__ unsigned g_zmin[2048];  // monotone-key min of su*(z + xnorm*u)
__device__ int   g_idx[2048];      // active column indices (padded with 0)
__device__ float g_b1g[2048];      // gathered b1
__device__ float g_sg[2048];       // gathered s
__device__ float g_base2[2048];    // s@W2 + b2
__device__ int   g_nact, g_nactpad;
__device__ unsigned g_xnmax_bits;

// ---------------- bf16 split arenas ------------------------------------------------
__device__ __nv_bfloat16 g_xs_hi[(size_t)BSZ * 1024];
__device__ __nv_bfloat16 g_xs_lo[(size_t)BSZ * 1024];
__device__ __nv_bfloat16 g_ds_hi[(size_t)BSZ * 512];
__device__ __nv_bfloat16 g_ds_lo[(size_t)BSZ * 512];
__device__ __nv_bfloat16 g_v_hi[(size_t)BSZ * 2048];
__device__ __nv_bfloat16 g_v_lo[(size_t)BSZ * 2048];
__device__ __nv_bfloat16 g_a2_hi[(size_t)BSZ * 2048];
__device__ __nv_bfloat16 g_a2_lo[(size_t)BSZ * 2048];

// split weights
#define O_W1X   0u            // [2048][1024] X-part of act_w1, transposed
#define O_W1DG  2097152u      // [2048][512] gathered dist-part cols
#define O_W2G   3145728u      // [2048][2048] gathered act_w2 rows
#define O_A3    7340032u      // [256][2048]
#define WT_TOTAL 7864320u
__device__ __nv_bfloat16 g_wt_hi[WT_TOTAL];
__device__ __nv_bfloat16 g_wt_lo[WT_TOTAL];

// ---------------- small helpers ----------------------------------------------------
__device__ __forceinline__ uint32_t smem_u32(const void* p) {
    uint32_t a;
    asm("{ .reg .u64 t; cvta.to.shared.u64 t, %1; cvt.u32.u64 %0, t; }" : "=r"(a) : "l"(p));
    return a;
}
__device__ __forceinline__ void cp16(uint32_t sdst, const void* gsrc) {
    uint64_t g;
    asm("cvta.to.global.u64 %0, %1;" : "=l"(g) : "l"(gsrc));
    asm volatile("cp.async.cg.shared.global [%0], [%1], 16;" :: "r"(sdst), "l"(g) : "memory");
}
__device__ __forceinline__ void cp_commit() {
    asm volatile("cp.async.commit_group;" ::: "memory");
}
template <int N>
__device__ __forceinline__ void cp_wait() {
    asm volatile("cp.async.wait_group %0;" :: "n"(N) : "memory");
}
__device__ __forceinline__ void ldsm4(uint32_t& r0, uint32_t& r1, uint32_t& r2, uint32_t& r3,
                                      uint32_t a) {
    asm volatile("ldmatrix.sync.aligned.m8n8.x4.shared.b16 {%0,%1,%2,%3}, [%4];"
                 : "=r"(r0), "=r"(r1), "=r"(r2), "=r"(r3) : "r"(a));
}
__device__ __forceinline__ void mma16816(float* c, const uint32_t* a, const uint32_t* b) {
    asm volatile("mma.sync.aligned.m16n8k16.row.col.f32.bf16.bf16.f32 "
                 "{%0,%1,%2,%3}, {%4,%5,%6,%7}, {%8,%9}, {%0,%1,%2,%3};"
                 : "+f"(c[0]), "+f"(c[1]), "+f"(c[2]), "+f"(c[3])
                 : "r"(a[0]), "r"(a[1]), "r"(a[2]), "r"(a[3]), "r"(b[0]), "r"(b[1]));
}
__device__ __forceinline__ void split2(float v, __nv_bfloat16& h, __nv_bfloat16& l) {
    h = __float2bfloat16(v);
    l = __float2bfloat16(v - __bfloat162float(h));
}
// monotone float<->unsigned key (ascending order preserved)
__device__ __forceinline__ unsigned enc_key(float x) {
    int i = __float_as_int(x);
    return (i >= 0) ? ((unsigned)i | 0x80000000u) : (unsigned)(~i);
}
__device__ __forceinline__ float dec_key(unsigned k) {
    int i = (k & 0x80000000u) ? (int)(k & 0x7FFFFFFFu) : (int)(~k);
    return __int_as_float(i);
}
__device__ __forceinline__ float blockReduceSum(float v) {
    __shared__ float sh[32];
    int lane = threadIdx.x & 31, wid = threadIdx.x >> 5;
#pragma unroll
    for (int o = 16; o > 0; o >>= 1) v += __shfl_down_sync(0xffffffffu, v, o);
    if (lane == 0) sh[wid] = v;
    __syncthreads();
    int nw = blockDim.x >> 5;
    v = (threadIdx.x < nw) ? sh[threadIdx.x] : 0.f;
    if (wid == 0) {
#pragma unroll
        for (int o = 16; o > 0; o >>= 1) v += __shfl_down_sync(0xffffffffu, v, o);
    }
    __syncthreads();
    return v;
}

// ---------------- tensor-core GEMM -------------------------------------------------
// EPI: 0 = acc+bias, 1 = tanh(acc+bias), 2 = v-epilogue (tanh(..)-sg, zero pad)
// ADDIN: += Cin. IDXIN: Cin column indexed via g_idx. KDEV: K = g_nactpad.
// NDYN: column tiles beyond g_nactpad exit.
#define PITCH 40
#define ST_A_H 0
#define ST_A_L 5120
#define ST_B_H 10240
#define ST_B_L 15360
#define ST_STRIDE 20480
#define STAGES 3
#define GEMM_SMEM (STAGES * ST_STRIDE * 2)

template <int EPI, int WF32, int WSPLIT, int ADDIN, int IDXIN, int KDEV, int NDYN>
__global__ void __launch_bounds__(256, 1)
mma_gemm(const __nv_bfloat16* __restrict__ Ah, const __nv_bfloat16* __restrict__ Al,
         int lda,
         const __nv_bfloat16* __restrict__ Wh, const __nv_bfloat16* __restrict__ Wl,
         int ldb, const float* __restrict__ bias, const float* __restrict__ Cin,
         float* __restrict__ Cf, __nv_bfloat16* __restrict__ Ch,
         __nv_bfloat16* __restrict__ Cl, int N, int Kst) {
    const int n0 = blockIdx.x * 128;
    if (NDYN && n0 >= g_nactpad) return;
    const int K = KDEV ? g_nactpad : Kst;
    const int nk = K >> 5;

    extern __shared__ __nv_bfloat16 sm[];
    __shared__ float s_bias[128];
    const int tid = threadIdx.x;
    const int lane = tid & 31, wid = tid >> 5;
    const int wm = wid >> 2, wn = wid & 3;
    const int m0 = blockIdx.y * 128;
    const uint32_t smb = smem_u32(sm);

    if (tid < 128) s_bias[tid] = bias[n0 + tid];
    __syncthreads();

    const int crow = tid >> 1;
    const int ck = (tid & 1) * 16;
    const uint32_t srow = (uint32_t)(crow * PITCH + ck) * 2;

    float acc[4][4][4];
#pragma unroll
    for (int i = 0; i < 4; i++)
#pragma unroll
        for (int j = 0; j < 4; j++)
#pragma unroll
            for (int q = 0; q < 4; q++) acc[i][j][q] = 0.f;

#define LOADSTAGE(SBASE, KK)                                                          \
    do {                                                                              \
        int k0 = (KK) + ck;                                                           \
        const __nv_bfloat16* pah = Ah + (size_t)(m0 + crow) * lda + k0;               \
        const __nv_bfloat16* pal = Al + (size_t)(m0 + crow) * lda + k0;               \
        const __nv_bfloat16* pbh = Wh + (size_t)(n0 + crow) * ldb + k0;               \
        const __nv_bfloat16* pbl = Wl + (size_t)(n0 + crow) * ldb + k0;               \
        cp16((SBASE) + ST_A_H * 2 + srow,      pah);                                  \
        cp16((SBASE) + ST_A_H * 2 + srow + 16, pah + 8);                              \
        cp16((SBASE) + ST_A_L * 2 + srow,      pal);                                  \
        cp16((SBASE) + ST_A_L * 2 + srow + 16, pal + 8);                              \
        cp16((SBASE) + ST_B_H * 2 + srow,      pbh);                                  \
        cp16((SBASE) + ST_B_H * 2 + srow + 16, pbh + 8);                              \
        cp16((SBASE) + ST_B_L * 2 + srow,      pbl);                                  \
        cp16((SBASE) + ST_B_L * 2 + srow + 16, pbl + 8);                              \
        cp_commit();                                                                  \
    } while (0)

    if (nk > 0) {
#pragma unroll
        for (int s = 0; s < STAGES - 1; ++s)
            if (s < nk) LOADSTAGE(smb + (uint32_t)s * (ST_STRIDE * 2), s * 32);

        const int fr = lane & 15;
        const int fc = (lane >> 4) << 3;
        for (int t = 0; t < nk; ++t) {
            cp_wait<STAGES - 2>();
            __syncthreads();
            uint32_t sb = smb + (uint32_t)(t % STAGES) * (ST_STRIDE * 2);
#pragma unroll
            for (int ks = 0; ks < 2; ++ks) {
                uint32_t ah[4][4], al[4][4], bh[4][2], bl[4][2];
#pragma unroll
                for (int mt = 0; mt < 4; ++mt) {
                    uint32_t a = sb + ST_A_H * 2 +
                                 (uint32_t)((wm * 64 + mt * 16 + fr) * PITCH + ks * 16 + fc) * 2;
                    ldsm4(ah[mt][0], ah[mt][1], ah[mt][2], ah[mt][3], a);
                    ldsm4(al[mt][0], al[mt][1], al[mt][2], al[mt][3],
                          a + (ST_A_L - ST_A_H) * 2);
                }
#pragma unroll
                for (int pn = 0; pn < 2; ++pn) {
                    uint32_t a = sb + ST_B_H * 2 +
                                 (uint32_t)((wn * 32 + pn * 16 + fr) * PITCH + ks * 16 + fc) * 2;
                    uint32_t r0, r1, r2, r3;
                    ldsm4(r0, r1, r2, r3, a);
                    bh[pn * 2][0] = r0; bh[pn * 2][1] = r2;
                    bh[pn * 2 + 1][0] = r1; bh[pn * 2 + 1][1] = r3;
                    ldsm4(r0, r1, r2, r3, a + (ST_B_L - ST_B_H) * 2);
                    bl[pn * 2][0] = r0; bl[pn * 2][1] = r2;
                    bl[pn * 2 + 1][0] = r1; bl[pn * 2 + 1][1] = r3;
                }
#pragma unroll
                for (int mt = 0; mt < 4; ++mt)
#pragma unroll
                    for (int nt = 0; nt < 4; ++nt) {
                        mma16816(acc[mt][nt], ah[mt], bh[nt]);
                        mma16816(acc[mt][nt], ah[mt], bl[nt]);
                        mma16816(acc[mt][nt], al[mt], bh[nt]);
                    }
            }
            __syncthreads();
            int tn = t + STAGES - 1;
            if (tn < nk) LOADSTAGE(smb + (uint32_t)(tn % STAGES) * (ST_STRIDE * 2), tn * 32);
        }
    }

    const int er = lane >> 2;
    const int ec = (lane & 3) * 2;
    const int nact = (EPI == 2) ? g_nact : 0;
#pragma unroll
    for (int mt = 0; mt < 4; ++mt) {
#pragma unroll
        for (int nt = 0; nt < 4; ++nt) {
            int col = wn * 32 + nt * 8 + ec;
            float b0 = s_bias[col], b1 = s_bias[col + 1];
#pragma unroll
            for (int h = 0; h < 2; ++h) {
                int row = m0 + wm * 64 + mt * 16 + er + h * 8;
                size_t off = (size_t)row * N + n0 + col;
                float v0 = acc[mt][nt][h * 2 + 0] + b0;
                float v1 = acc[mt][nt][h * 2 + 1] + b1;
                if (ADDIN) {
                    if (IDXIN) {
                        v0 += Cin[(size_t)row * 2048 + g_idx[n0 + col]];
                        v1 += Cin[(size_t)row * 2048 + g_idx[n0 + col + 1]];
                    } else {
                        float2 ci = *(const float2*)(Cin + off);
                        v0 += ci.x;
                        v1 += ci.y;
                    }
                }
                if (EPI == 1) { v0 = tanhf(v0); v1 = tanhf(v1); }
                if (EPI == 2) {
                    v0 = tanhf(v0) - g_sg[n0 + col];
                    v1 = tanhf(v1) - g_sg[n0 + col + 1];
                    if (n0 + col >= nact) v0 = 0.f;
                    if (n0 + col + 1 >= nact) v1 = 0.f;
                }
                if (WF32) *(float2*)(Cf + off) = make_float2(v0, v1);
                if (WSPLIT) {
                    __nv_bfloat16 h0, l0, h1, l1;
                    split2(v0, h0, l0);
                    split2(v1, h1, l1);
                    __nv_bfloat162 ph, pl;
                    ph.x = h0; ph.y = h1;
                    pl.x = l0; pl.y = l1;
                    *(__nv_bfloat162*)(Ch + off) = ph;
                    *(__nv_bfloat162*)(Cl + off) = pl;
                }
            }
        }
    }
#undef LOADSTAGE
}

// ---------------- FFMA SGEMM (fp32-exact) --------------------------------------------
#define BM 128
#define BN 128
#define BK 8

template <int EPI, int WC, int SPLITOUT>   // EPI 0:+bias 1:tanh 2:dist
__global__ void __launch_bounds__(256)
sgemm_kernel(const float* __restrict__ A, const float* __restrict__ B,
             const float* __restrict__ bias, const float* __restrict__ rown,
             float* __restrict__ C, __nv_bfloat16* __restrict__ Dh,
             __nv_bfloat16* __restrict__ Dl, int K, int ldb, int ldc) {
    __shared__ __align__(16) float As[2][BK][BM];
    __shared__ __align__(16) float Bs[2][BK][BN];
    const int tid = threadIdx.x;
    const int tx = tid & 15, ty = tid >> 4;
    const int m0 = blockIdx.y * BM, n0 = blockIdx.x * BN;
    const int arow = tid >> 1, akq = (tid & 1) * 4;
    const float* Aptr = A + (size_t)(m0 + arow) * K + akq;
    const int brow = tid >> 5, bcol = (tid & 31) * 4;
    const float* Bptr = B + (size_t)brow * ldb + n0 + bcol;
    float acc[8][8];
#pragma unroll
    for (int i = 0; i < 8; i++)
#pragma unroll
        for (int j = 0; j < 8; j++) acc[i][j] = 0.f;
    const int nt = K / BK;
    float4 a4 = *(const float4*)(Aptr);
    float4 b4 = *(const float4*)(Bptr);
    As[0][akq + 0][arow] = a4.x; As[0][akq + 1][arow] = a4.y;
    As[0][akq + 2][arow] = a4.z; As[0][akq + 3][arow] = a4.w;
    *(float4*)&Bs[0][brow][bcol] = b4;
    __syncthreads();
    int cur = 0;
    for (int t = 0; t < nt; t++) {
        if (t + 1 < nt) {
            a4 = *(const float4*)(Aptr + (t + 1) * BK);
            b4 = *(const float4*)(Bptr + (size_t)(t + 1) * BK * ldb);
        }
#pragma unroll
        for (int kk = 0; kk < BK; kk++) {
            float4 a0 = *(const float4*)&As[cur][kk][ty * 4];
            float4 a1 = *(const float4*)&As[cur][kk][64 + ty * 4];
            float4 b0 = *(const float4*)&Bs[cur][kk][tx * 4];
            float4 b1 = *(const float4*)&Bs[cur][kk][64 + tx * 4];
            float ar[8] = {a0.x, a0.y, a0.z, a0.w, a1.x, a1.y, a1.z, a1.w};
            float br[8] = {b0.x, b0.y, b0.z, b0.w, b1.x, b1.y, b1.z, b1.w};
#pragma unroll
            for (int i = 0; i < 8; i++)
#pragma unroll
                for (int j = 0; j < 8; j++) acc[i][j] = fmaf(ar[i], br[j], acc[i][j]);
        }
        if (t + 1 < nt) {
            int nx = cur ^ 1;
            As[nx][akq + 0][arow] = a4.x; As[nx][akq + 1][arow] = a4.y;
            As[nx][akq + 2][arow] = a4.z; As[nx][akq + 3][arow] = a4.w;
            *(float4*)&Bs[nx][brow][bcol] = b4;
        }
        __syncthreads();
        cur ^= 1;
    }
#pragma unroll
    for (int i = 0; i < 8; i++) {
        int r = m0 + ((i < 4) ? (ty * 4 + i) : (64 + ty * 4 + (i - 4)));
        float rn = (EPI == 2) ? rown[r] : 0.f;
#pragma unroll
        for (int jh = 0; jh < 2; jh++) {
            int c = n0 + jh * 64 + tx * 4;
            float4 bv = *(const float4*)(bias + c);
            const float* ap = &acc[i][jh * 4];
            float4 v;
            if (EPI == 2) {
                v.x = rn + bv.x - 2.f * ap[0];
                v.y = rn + bv.y - 2.f * ap[1];
                v.z = rn + bv.z - 2.f * ap[2];
                v.w = rn + bv.w - 2.f * ap[3];
            } else {
                v.x = ap[0] + bv.x; v.y = ap[1] + bv.y;
                v.z = ap[2] + bv.z; v.w = ap[3] + bv.w;
                if (EPI == 1) {
                    v.x = tanhf(v.x); v.y = tanhf(v.y);
                    v.z = tanhf(v.z); v.w = tanhf(v.w);
                }
            }
            size_t off = (size_t)r * ldc + c;
            if (WC) *(float4*)(C + off) = v;
            if (SPLITOUT) {
                __nv_bfloat16 h0, l0, h1, l1, h2, l2, h3, l3;
                split2(v.x, h0, l0); split2(v.y, h1, l1);
                split2(v.z, h2, l2); split2(v.w, h3, l3);
                __nv_bfloat162 ph0, ph1, pl0, pl1;
                ph0.x = h0; ph0.y = h1; ph1.x = h2; ph1.y = h3;
                pl0.x = l0; pl0.y = l1; pl1.x = l2; pl1.y = l3;
                *(__nv_bfloat162*)(Dh + off) = ph0;
                *(__nv_bfloat162*)(Dh + off + 2) = ph1;
                *(__nv_bfloat162*)(Dl + off) = pl0;
                *(__nv_bfloat162*)(Dl + off + 2) = pl1;
            }
        }
    }
}

// ---------------- analysis kernels ----------------------------------------------------
__global__ void reset_stats_kernel() {
    int t = threadIdx.x;  // 256
    for (int j = t; j < 2048; j += 256) g_zmin[j] = 0xFFFFFFFFu;
    if (t == 0) {
        g_xnmax_bits = 0u;
        g_nact = 0;
        g_nactpad = 0;
    }
}

__global__ void prep_codebook_kernel(const float* __restrict__ cb) {
    int k = blockIdx.x;
    float s = 0.f;
    for (int d = threadIdx.x; d < OBS; d += blockDim.x) {
        float v = cb[(size_t)k * OBS + d];
        g_cbT[(size_t)d * KCB + k] = v;
        s += v * v;
    }
    s = blockReduceSum(s);
    if (threadIdx.x == 0) g_cnorm[k] = s;
}

// per-column of act_w1 dist-part: u_j, c_j = cnorm.W1d_j, sign
__global__ void colstats_kernel(const float* __restrict__ W1) {
    int j = blockIdx.x;
    float u = 0.f, c = 0.f;
    for (int k = threadIdx.x; k < 512; k += blockDim.x) {
        float w = W1[(size_t)(1024 + k) * 2048 + j];
        u += w;
        c += g_cnorm[k] * w;
    }
    u = blockReduceSum(u);
    c = blockReduceSum(c);
    if (threadIdx.x == 0) {
        g_colU[j] = u;
        g_colC[j] = c;
        g_sj[j] = (u > 0.f) ? 1.f : -1.f;
    }
}

__global__ void rownorm_kernel(const float* __restrict__ x) {
    int b = blockIdx.x;
    const float* r = x + (size_t)b * OBS;
    float s = 0.f;
    for (int d = threadIdx.x; d < OBS; d += blockDim.x) {
        float v = r[d];
        s += v * v;
    }
    s = blockReduceSum(s);
    if (threadIdx.x == 0) {
        g_xnorm[b] = s;
        atomicMax(&g_xnmax_bits, __float_as_uint(s));
    }
}

// 2*||M2 col j||
__global__ void m2norm_kernel() {
    int j = blockIdx.x;
    float s = 0.f;
    for (int r = threadIdx.x; r < 1024; r += blockDim.x) {
        float v = g_M2[(size_t)r * 2048 + j];
        s += v * v;
    }
    s = blockReduceSum(s);
    if (threadIdx.x == 0) g_m2n[j] = 2.f * sqrtf(s);
}

// per-column min over rows of su_j*z + xnorm*|u_j|
__global__ void zstats_kernel() {
    int b0 = blockIdx.x * 128;  // 256 blocks
    float best[8];
#pragma unroll
    for (int i = 0; i < 8; i++) best[i] = INFINITY;
    for (int r = b0; r < b0 + 128; ++r) {
        float xn = g_xnorm[r];
        const float* zr = g_z + (size_t)r * 2048;
#pragma unroll
        for (int it = 0; it < 8; ++it) {
            int j = threadIdx.x + it * 256;
            float f = g_sj[j] * zr[j] + xn * fabsf(g_colU[j]);
            if (f < best[it]) best[it] = f;
        }
    }
#pragma unroll
    for (int it = 0; it < 8; ++it) {
        int j = threadIdx.x + it * 256;
        atomicMin(&g_zmin[j], enc_key(best[it]));
    }
}

__global__ void activity_kernel(const float* __restrict__ b1) {
    __shared__ int flags[2048];
    float xn_s = sqrtf(__uint_as_float(g_xnmax_bits));
    for (int j = threadIdx.x; j < 2048; j += blockDim.x) {
        float slack = dec_key(g_zmin[j]) + g_sj[j] * (g_colC[j] + b1[j])
                      - 1.01f * xn_s * g_m2n[j] - 0.05f;
        flags[j] = (slack < 10.f) ? 1 : 0;  // active
    }
    __syncthreads();
    if (threadIdx.x == 0) {
        int c = 0;
        for (int j = 0; j < 2048; ++j)
            if (flags[j]) g_idx[c++] = j;
        g_nact = c;
        g_nactpad = (c + 127) & ~127;
        for (int j = c; j < 2048; ++j) g_idx[j] = 0;
    }
}

// gather dist-part W1 cols -> [n][512] splits; b1g, sg
__global__ void gatherW1d_kernel(const float* __restrict__ W1, const float* __restrict__ b1,
                                 __nv_bfloat16* __restrict__ hi, __nv_bfloat16* __restrict__ lo) {
    int n = blockIdx.x;
    if (n >= g_nactpad) return;
    int j = (n < g_nact) ? g_idx[n] : -1;
    for (int k = threadIdx.x; k < 512; k += blockDim.x) {
        float w = (j >= 0) ? W1[(size_t)(1024 + k) * 2048 + j] : 0.f;
        __nv_bfloat16 h, l;
        split2(w, h, l);
        hi[(size_t)n * 512 + k] = h;
        lo[(size_t)n * 512 + k] = l;
    }
    if (threadIdx.x == 0) {
        g_b1g[n] = (j >= 0) ? b1[j] : 0.f;
        g_sg[n] = (j >= 0) ? g_sj[j] : 0.f;
    }
}

__global__ void gatherW2_kernel(const float* __restrict__ W2,
                                __nv_bfloat16* __restrict__ hi, __nv_bfloat16* __restrict__ lo) {
    int n = blockIdx.x;
    int np = g_nactpad;
    for (int i = threadIdx.x; i < np; i += blockDim.x) {
        float w = (i < g_nact) ? W2[(size_t)g_idx[i] * 2048 + n] : 0.f;
        __nv_bfloat16 h, l;
        split2(w, h, l);
        hi[(size_t)n * 2048 + i] = h;
        lo[(size_t)n * 2048 + i] = l;
    }
}

__global__ void base2_kernel(const float* __restrict__ W2, const float* __restrict__ b2) {
    int n = blockIdx.x;
    float s = 0.f;
    for (int j = threadIdx.x; j < 2048; j += blockDim.x)
        s += g_sj[j] * W2[(size_t)j * 2048 + n];
    s = blockReduceSum(s);
    if (threadIdx.x == 0) g_base2[n] = s + b2[n];
}

__global__ void argmin_kernel(const float* __restrict__ dist, float* __restrict__ prop_out_f) {
    __shared__ float sv[256];
    __shared__ int si[256];
    int b = blockIdx.x;
    const float* r = dist + (size_t)b * KCB;
    float best = INFINITY;
    int bi = KCB;
    for (int k = threadIdx.x; k < KCB; k += 256) {
        float v = r[k];
        if (v < best) { best = v; bi = k; }
    }
    sv[threadIdx.x] = best;
    si[threadIdx.x] = bi;
    __syncthreads();
    for (int s = 128; s > 0; s >>= 1) {
        if (threadIdx.x < s) {
            float ov = sv[threadIdx.x + s];
            int oi = si[threadIdx.x + s];
            if (ov < sv[threadIdx.x] || (ov == sv[threadIdx.x] && oi < si[threadIdx.x])) {
                sv[threadIdx.x] = ov;
                si[threadIdx.x] = oi;
            }
        }
        __syncthreads();
    }
    if (threadIdx.x == 0) {
        g_prop[b] = si[0];
        prop_out_f[b] = (float)si[0];
    }
}

__global__ void xsplit_kernel(const float* __restrict__ X, __nv_bfloat16* __restrict__ xh,
                              __nv_bfloat16* __restrict__ xl) {
    size_t i = (size_t)blockIdx.x * blockDim.x + threadIdx.x;
    float v = X[i];
    __nv_bfloat16 h, l;
    split2(v, h, l);
    xh[i] = h;
    xl[i] = l;
}

// transpose+split: W[K,N] f32 -> [N,K] bf16 hi/lo
__global__ void wsplit_kernel(const float* __restrict__ W, __nv_bfloat16* __restrict__ hi,
                              __nv_bfloat16* __restrict__ lo, int K, int N) {
    __shared__ float t[32][33];
    const int n0 = blockIdx.x * 32, k0 = blockIdx.y * 32;
    const int tx = threadIdx.x, ty = threadIdx.y;
#pragma unroll
    for (int i = 0; i < 4; i++)
        t[ty + i * 8][tx] = W[(size_t)(k0 + ty + i * 8) * N + n0 + tx];
    __syncthreads();
#pragma unroll
    for (int i = 0; i < 4; i++) {
        int n = ty + i * 8;
        float v = t[tx][n];
        __nv_bfloat16 h, l;
        split2(v, h, l);
        size_t o = (size_t)(n0 + n) * K + k0 + tx;
        hi[o] = h;
        lo[o] = l;
    }
}

__global__ void loss_partial_kernel(const float* __restrict__ dx, const float* __restrict__ cb) {
    const size_t NTOT = (size_t)BSZ * OBS;
    float s1 = 0.f, s2 = 0.f;
    for (size_t i = (size_t)blockIdx.x * blockDim.x + threadIdx.x; i < NTOT;
         i += (size_t)gridDim.x * blockDim.x) {
        int b = (int)(i >> 10);
        int d = (int)(i & 1023);
        size_t ko = (size_t)g_prop[b] * OBS + d;
        float a = dx[i] - g_cb_recon[ko];
        s1 += a * a;
        float c = g_enc[i] - cb[ko];
        s2 += c * c;
    }
    s1 = blockReduceSum(s1);
    __syncthreads();
    s2 = blockReduceSum(s2);
    if (threadIdx.x == 0) {
        g_part[2 * blockIdx.x + 0] = s1;
        g_part[2 * blockIdx.x + 1] = s2;
    }
}

__global__ void finalize_total_kernel(int nb, float* __restrict__ out_total) {
    float s1 = 0.f, s2 = 0.f;
    for (int i = threadIdx.x; i < nb; i += 256) {
        s1 += g_part[2 * i + 0];
        s2 += g_part[2 * i + 1];
    }
    s1 = blockReduceSum(s1);
    __syncthreads();
    s2 = blockReduceSum(s2);
    if (threadIdx.x == 0) {
        const float inv = 1.f / ((float)BSZ * (float)OBS);
        float tot = s1 * inv + 2.f * (s2 * inv);
        g_total[0] = tot;
        out_total[0] = tot;
    }
}

__global__ void policy_kernel(const float* __restrict__ A_, const float* __restrict__ log_std,
                              float* __restrict__ out_loss, float* __restrict__ out_losspi) {
    int b = blockIdx.x;
    int j = threadIdx.x;
    float ls = log_std[j];
    float sd = expf(ls);
    float z = (A_[(size_t)b * OUTD + j] - g_mu[(size_t)b * OUTD + j]) / sd;
    float logp = -0.5f * z * z - ls - 0.5f * LOG2PI_F;
    float term = 1.f / (expf(logp) + 0.1f);
    float lp = blockReduceSum(term);
    if (threadIdx.x == 0) {
        out_losspi[b] = lp;
        out_loss[b] = lp * g_total[0];
    }
}

// ---------------- launch ----------------------------------------------------------------
extern "C" void kernel_launch(void* const* d_in, const int* in_sizes, int n_in,
                              void* d_out, int out_size) {
    const float* X        = (const float*)d_in[0];
    const float* Delta_X  = (const float*)d_in[1];
    const float* A        = (const float*)d_in[2];
    const float* enc_w1   = (const float*)d_in[3];
    const float* enc_b1   = (const float*)d_in[4];
    const float* enc_w2   = (const float*)d_in[5];
    const float* enc_b2   = (const float*)d_in[6];
    const float* prenet_w = (const float*)d_in[7];
    const float* prenet_b = (const float*)d_in[8];
    const float* codebook = (const float*)d_in[9];
    const float* postnet_w= (const float*)d_in[10];
    const float* postnet_b= (const float*)d_in[11];
    const float* dec_w1   = (const float*)d_in[12];
    const float* dec_b1   = (const float*)d_in[13];
    const float* dec_w2   = (const float*)d_in[14];
    const float* dec_b2   = (const float*)d_in[15];
    const float* dec_w3   = (const float*)d_in[16];
    const float* dec_b3   = (const float*)d_in[17];
    const float* act_w1   = (const float*)d_in[18];
    const float* act_b1   = (const float*)d_in[19];
    const float* act_w2   = (const float*)d_in[20];
    const float* act_b2   = (const float*)d_in[21];
    const float* act_w3   = (const float*)d_in[22];
    const float* act_b3   = (const float*)d_in[23];
    const float* log_std  = (const float*)d_in[24];

    float* out = (float*)d_out;
    float* out_loss   = out;
    float* out_losspi = out + BSZ;
    float* out_X      = out + 2 * (size_t)BSZ;
    float* out_prop   = out + 2 * (size_t)BSZ + (size_t)BSZ * OBS;
    float* out_total  = out_prop + BSZ;

    float *p_h1, *p_h2, *p_enc, *p_dist, *p_mu, *p_cbT, *p_cnorm, *p_xnorm, *p_zb, *p_z, *p_M2;
    float *p_d0, *p_d1, *p_d2, *p_rec, *p_base2, *p_b1g;
    __nv_bfloat16 *p_wh, *p_wl, *p_xh, *p_xl, *p_dh, *p_dl, *p_vh, *p_vl, *p_a2h, *p_a2l;
    cudaGetSymbolAddress((void**)&p_h1, g_h1);
    cudaGetSymbolAddress((void**)&p_h2, g_h2);
    cudaGetSymbolAddress((void**)&p_enc, g_enc);
    cudaGetSymbolAddress((void**)&p_dist, g_dist);
    cudaGetSymbolAddress((void**)&p_mu, g_mu);
    cudaGetSymbolAddress((void**)&p_cbT, g_cbT);
    cudaGetSymbolAddress((void**)&p_cnorm, g_cnorm);
    cudaGetSymbolAddress((void**)&p_xnorm, g_xnorm);
    cudaGetSymbolAddress((void**)&p_zb, g_zb);
    cudaGetSymbolAddress((void**)&p_z, g_z);
    cudaGetSymbolAddress((void**)&p_M2, g_M2);
    cudaGetSymbolAddress((void**)&p_d0, g_cb_d0);
    cudaGetSymbolAddress((void**)&p_d1, g_cb_d1);
    cudaGetSymbolAddress((void**)&p_d2, g_cb_d2);
    cudaGetSymbolAddress((void**)&p_rec, g_cb_recon);
    cudaGetSymbolAddress((void**)&p_base2, g_base2);
    cudaGetSymbolAddress((void**)&p_b1g, g_b1g);
    cudaGetSymbolAddress((void**)&p_wh, g_wt_hi);
    cudaGetSymbolAddress((void**)&p_wl, g_wt_lo);
    cudaGetSymbolAddress((void**)&p_xh, g_xs_hi);
    cudaGetSymbolAddress((void**)&p_xl, g_xs_lo);
    cudaGetSymbolAddress((void**)&p_dh, g_ds_hi);
    cudaGetSymbolAddress((void**)&p_dl, g_ds_lo);
    cudaGetSymbolAddress((void**)&p_vh, g_v_hi);
    cudaGetSymbolAddress((void**)&p_vl, g_v_lo);
    cudaGetSymbolAddress((void**)&p_a2h, g_a2_hi);
    cudaGetSymbolAddress((void**)&p_a2l, g_a2_lo);

    cudaFuncSetAttribute(mma_gemm<0, 1, 0, 0, 0, 0, 0>, cudaFuncAttributeMaxDynamicSharedMemorySize, GEMM_SMEM);
    cudaFuncSetAttribute(mma_gemm<2, 0, 1, 1, 1, 0, 1>, cudaFuncAttributeMaxDynamicSharedMemorySize, GEMM_SMEM);
    cudaFuncSetAttribute(mma_gemm<1, 0, 1, 0, 0, 1, 0>, cudaFuncAttributeMaxDynamicSharedMemorySize, GEMM_SMEM);

    static cudaStream_t s2 = nullptr, s3 = nullptr;
    static cudaEvent_t evRoot = nullptr, evS2 = nullptr, evArg = nullptr, evTot = nullptr,
                       evAct = nullptr, evG = nullptr, evPrep = nullptr, evM2 = nullptr;
    if (s2 == nullptr) {
        cudaStreamCreateWithFlags(&s2, cudaStreamNonBlocking);
        cudaStreamCreateWithFlags(&s3, cudaStreamNonBlocking);
        cudaEventCreateWithFlags(&evRoot, cudaEventDisableTiming);
        cudaEventCreateWithFlags(&evS2, cudaEventDisableTiming);
        cudaEventCreateWithFlags(&evArg, cudaEventDisableTiming);
        cudaEventCreateWithFlags(&evTot, cudaEventDisableTiming);
        cudaEventCreateWithFlags(&evAct, cudaEventDisableTiming);
        cudaEventCreateWithFlags(&evG, cudaEventDisableTiming);
        cudaEventCreateWithFlags(&evPrep, cudaEventDisableTiming);
        cudaEventCreateWithFlags(&evM2, cudaEventDisableTiming);
    }

    dim3 tb(32, 8);

    cudaEventRecord(evRoot, 0);
    cudaStreamWaitEvent(s2, evRoot, 0);

    // ---------- s2: act3 weight split, decoder-512, out_X, losses ----------
    wsplit_kernel<<<dim3(256 / 32, 2048 / 32), tb, 0, s2>>>(act_w3, p_wh + O_A3, p_wl + O_A3, 2048, 256);
    cudaEventRecord(evS2, s2);
    sgemm_kernel<1, 1, 0><<<dim3(1024 / BN, KCB / BM), 256, 0, s2>>>(codebook, postnet_w, postnet_b, nullptr, p_d0, nullptr, nullptr, 1024, 1024, 1024);
    sgemm_kernel<1, 1, 0><<<dim3(2048 / BN, KCB / BM), 256, 0, s2>>>(p_d0, dec_w1, dec_b1, nullptr, p_d1, nullptr, nullptr, 1024, 2048, 2048);
    sgemm_kernel<1, 1, 0><<<dim3(2048 / BN, KCB / BM), 256, 0, s2>>>(p_d1, dec_w2, dec_b2, nullptr, p_d2, nullptr, nullptr, 2048, 2048, 2048);
    sgemm_kernel<0, 1, 0><<<dim3(1024 / BN, KCB / BM), 256, 0, s2>>>(p_d2, dec_w3, dec_b3, nullptr, p_rec, nullptr, nullptr, 2048, 1024, 1024);
    cudaMemcpyAsync(out_X, X, (size_t)BSZ * OBS * sizeof(float), cudaMemcpyDeviceToDevice, s2);

    // ---------- main: prep, z GEMM, encoder ----------
    reset_stats_kernel<<<1, 256>>>();
    prep_codebook_kernel<<<KCB, 256>>>(codebook);
    colstats_kernel<<<2048, 256>>>(act_w1);
    cudaEventRecord(evPrep, 0);

    // ---------- s3: M2 = cbT @ W1d, column norms ----------
    cudaStreamWaitEvent(s3, evPrep, 0);
    sgemm_kernel<0, 1, 0><<<dim3(2048 / BN, 1024 / BM), 256, 0, s3>>>(
        p_cbT, act_w1 + (size_t)1024 * 2048, p_zb, nullptr, p_M2, nullptr, nullptr, 512, 2048, 2048);
    m2norm_kernel<<<2048, 256, 0, s3>>>();
    cudaEventRecord(evM2, s3);

    // main: X split, W1x split, z = X@W1x (all 2048 cols)
    xsplit_kernel<<<(BSZ * OBS) / 256, 256>>>(X, p_xh, p_xl);
    wsplit_kernel<<<dim3(2048 / 32, 1024 / 32), tb>>>(act_w1, p_wh + O_W1X, p_wl + O_W1X, 1024, 2048);
    mma_gemm<0, 1, 0, 0, 0, 0, 0><<<dim3(16, 256), 256, GEMM_SMEM>>>(
        p_xh, p_xl, 1024, p_wh + O_W1X, p_wl + O_W1X, 1024, p_zb, nullptr,
        p_z, nullptr, nullptr, 2048, 1024);

    // encoder (fp32)
    sgemm_kernel<1, 1, 0><<<dim3(512 / BN, BSZ / BM), 256>>>(Delta_X, enc_w1, enc_b1, nullptr, p_h1, nullptr, nullptr, 1024, 512, 512);
    sgemm_kernel<1, 1, 0><<<dim3(1024 / BN, BSZ / BM), 256>>>(p_h1, enc_w2, enc_b2, nullptr, p_h2, nullptr, nullptr, 512, 1024, 1024);
    sgemm_kernel<0, 1, 0><<<dim3(1024 / BN, BSZ / BM), 256>>>(p_h2, prenet_w, prenet_b, nullptr, p_enc, nullptr, nullptr, 1024, 1024, 1024);
    rownorm_kernel<<<BSZ, 256>>>(p_enc);
    zstats_kernel<<<256, 256>>>();
    cudaStreamWaitEvent(0, evM2, 0);
    activity_kernel<<<1, 1024>>>(act_b1);
    cudaEventRecord(evAct, 0);

    // ---------- s3: gathers + base2 (overlap dist GEMM) ----------
    cudaStreamWaitEvent(s3, evAct, 0);
    gatherW1d_kernel<<<2048, 256, 0, s3>>>(act_w1, act_b1, p_wh + O_W1DG, p_wl + O_W1DG);
    gatherW2_kernel<<<2048, 256, 0, s3>>>(act_w2, p_wh + O_W2G, p_wl + O_W2G);
    base2_kernel<<<2048, 256, 0, s3>>>(act_w2, act_b2);
    cudaEventRecord(evG, s3);

    // ---------- main: distances + argmin ----------
    sgemm_kernel<2, 1, 1><<<dim3(KCB / BN, BSZ / BM), 256>>>(p_enc, p_cbT, p_cnorm, p_xnorm, p_dist, p_dh, p_dl, OBS, KCB, KCB);
    argmin_kernel<<<BSZ, 256>>>(p_dist, out_prop);
    cudaEventRecord(evArg, 0);

    // ---------- s2: VQ losses ----------
    cudaStreamWaitEvent(s2, evArg, 0);
    loss_partial_kernel<<<2048, 256, 0, s2>>>(Delta_X, codebook);
    finalize_total_kernel<<<1, 256, 0, s2>>>(2048, out_total);
    cudaEventRecord(evTot, s2);

    // ---------- main: actor (active columns only) ----------
    cudaStreamWaitEvent(0, evG, 0);
    cudaStreamWaitEvent(0, evS2, 0);
    // v = tanh(z[gathered] + dist@W1dg + b1g) - s  (K=512, only nactpad col tiles)
    mma_gemm<2, 0, 1, 1, 1, 0, 1><<<dim3(16, 256), 256, GEMM_SMEM>>>(
        p_dh, p_dl, 512, p_wh + O_W1DG, p_wl + O_W1DG, 512, p_b1g, p_z,
        nullptr, p_vh, p_vl, 2048, 512);
    // a2 = tanh(base2 + v@W2g), K = nactpad (device)
    mma_gemm<1, 0, 1, 0, 0, 1, 0><<<dim3(16, 256), 256, GEMM_SMEM>>>(
        p_vh, p_vl, 2048, p_wh + O_W2G, p_wl + O_W2G, 2048, p_base2, nullptr,
        nullptr, p_a2h, p_a2l, 2048, 0);
    // mu
    mma_gemm<0, 1, 0, 0, 0, 0, 0><<<dim3(2, 256), 256, GEMM_SMEM>>>(
        p_a2h, p_a2l, 2048, p_wh + O_A3, p_wl + O_A3, 2048, act_b3, nullptr,
        p_mu, nullptr, nullptr, 256, 2048);

    cudaStreamWaitEvent(0, evTot, 0);
    policy_kernel<<<BSZ, 256>>>(A, log_std, out_loss, out_losspi);
}

// round 12
// speedup vs baseline: 1.0019x; 1.0019x over previous
#include <cuda_runtime.h>
#include <cuda_bf16.h>
#include <math.h>
#include <stdint.h>

#define BSZ   32768
#define OBS   1024
#define OUTD  256
#define KCB   512
#define LOG2PI_F 1.83787706640934534f

// ---------------- fp32 scratch ---------------------------------------------------
__device__ float g_cbT[OBS * KCB];
__device__ float g_cnorm[KCB];
__device__ float g_xnorm[BSZ];
__device__ float g_h1[(size_t)BSZ * 512];
__device__ float g_h2[(size_t)BSZ * 1024];
__device__ float g_enc[(size_t)BSZ * 1024];
__device__ float g_dist[(size_t)BSZ * 512];
__device__ int   g_prop[BSZ];
__device__ float g_mu[(size_t)BSZ * 256];
__device__ float g_part[2048 * 2];
__device__ float g_total[1];
__device__ float g_zb[2048];                   // stays zero
__device__ float g_p1[(size_t)BSZ * 2048];     // act1 X-part partial (fp32)

// decoder computed on the 512 unique codebook rows only
__device__ float g_cb_d0[(size_t)KCB * 1024];
__device__ float g_cb_d1[(size_t)KCB * 2048];
__device__ float g_cb_d2[(size_t)KCB * 2048];
__device__ float g_cb_recon[(size_t)KCB * 1024];

// ---------------- bf16 split arenas ------------------------------------------------
__device__ __nv_bfloat16 g_xs_hi[(size_t)BSZ * 1024];
__device__ __nv_bfloat16 g_xs_lo[(size_t)BSZ * 1024];
__device__ __nv_bfloat16 g_ds_hi[(size_t)BSZ * 512];
__device__ __nv_bfloat16 g_ds_lo[(size_t)BSZ * 512];
__device__ __nv_bfloat16 g_a1_hi[(size_t)BSZ * 2048];
__device__ __nv_bfloat16 g_a1_lo[(size_t)BSZ * 2048];
__device__ __nv_bfloat16 g_a2_hi[(size_t)BSZ * 2048];
__device__ __nv_bfloat16 g_a2_lo[(size_t)BSZ * 2048];

// transposed + split actor weights [N][K] bf16
#define O_W1X   0u            // [2048][1024]
#define O_W1D   2097152u      // [2048][512]
#define O_W2    3145728u      // [2048][2048]
#define O_A3    7340032u      // [256][2048]
#define WT_TOTAL 7864320u
__device__ __nv_bfloat16 g_wt_hi[WT_TOTAL];
__device__ __nv_bfloat16 g_wt_lo[WT_TOTAL];

// ---------------- small helpers ----------------------------------------------------
__device__ __forceinline__ uint32_t smem_u32(const void* p) {
    uint32_t a;
    asm("{ .reg .u64 t; cvta.to.shared.u64 t, %1; cvt.u32.u64 %0, t; }" : "=r"(a) : "l"(p));
    return a;
}
__device__ __forceinline__ void cp16(uint32_t sdst, const void* gsrc) {
    uint64_t g;
    asm("cvta.to.global.u64 %0, %1;" : "=l"(g) : "l"(gsrc));
    asm volatile("cp.async.cg.shared.global [%0], [%1], 16;" :: "r"(sdst), "l"(g) : "memory");
}
__device__ __forceinline__ void cp_commit() {
    asm volatile("cp.async.commit_group;" ::: "memory");
}
template <int N>
__device__ __forceinline__ void cp_wait() {
    asm volatile("cp.async.wait_group %0;" :: "n"(N) : "memory");
}
__device__ __forceinline__ void ldsm4(uint32_t& r0, uint32_t& r1, uint32_t& r2, uint32_t& r3,
                                      uint32_t a) {
    asm volatile("ldmatrix.sync.aligned.m8n8.x4.shared.b16 {%0,%1,%2,%3}, [%4];"
                 : "=r"(r0), "=r"(r1), "=r"(r2), "=r"(r3) : "r"(a));
}
__device__ __forceinline__ void mma16816(float* c, const uint32_t* a, const uint32_t* b) {
    asm volatile("mma.sync.aligned.m16n8k16.row.col.f32.bf16.bf16.f32 "
                 "{%0,%1,%2,%3}, {%4,%5,%6,%7}, {%8,%9}, {%0,%1,%2,%3};"
                 : "+f"(c[0]), "+f"(c[1]), "+f"(c[2]), "+f"(c[3])
                 : "r"(a[0]), "r"(a[1]), "r"(a[2]), "r"(a[3]), "r"(b[0]), "r"(b[1]));
}
__device__ __forceinline__ void split2(float v, __nv_bfloat16& h, __nv_bfloat16& l) {
    h = __float2bfloat16(v);
    l = __float2bfloat16(v - __bfloat162float(h));
}
__device__ __forceinline__ float blockReduceSum(float v) {
    __shared__ float sh[32];
    int lane = threadIdx.x & 31, wid = threadIdx.x >> 5;
#pragma unroll
    for (int o = 16; o > 0; o >>= 1) v += __shfl_down_sync(0xffffffffu, v, o);
    if (lane == 0) sh[wid] = v;
    __syncthreads();
    int nw = blockDim.x >> 5;
    v = (threadIdx.x < nw) ? sh[threadIdx.x] : 0.f;
    if (wid == 0) {
#pragma unroll
        for (int o = 16; o > 0; o >>= 1) v += __shfl_down_sync(0xffffffffu, v, o);
    }
    __syncthreads();
    return v;
}

// ---------------- tensor-core GEMM (R7-proven core) --------------------------------
// EPI: 0 = acc+bias, 1 = tanh(acc+bias).  ADDIN: += Cin[row*N+col].
// STG: pipeline stages.  MINB: launch_bounds minBlocksPerMultiprocessor.
#define PITCH 40
#define ST_A_H 0
#define ST_A_L 5120
#define ST_B_H 10240
#define ST_B_L 15360
#define ST_STRIDE 20480
#define MMA_SMEM(STG) ((STG) * ST_STRIDE * 2)

template <int EPI, int WF32, int WSPLIT, int ADDIN, int STG, int MINB>
__global__ void __launch_bounds__(256, MINB)
mma_gemm(const __nv_bfloat16* __restrict__ Ah, const __nv_bfloat16* __restrict__ Al,
         int lda,
         const __nv_bfloat16* __restrict__ Wh, const __nv_bfloat16* __restrict__ Wl,
         int ldb, const float* __restrict__ bias, const float* __restrict__ Cin,
         float* __restrict__ Cf, __nv_bfloat16* __restrict__ Ch,
         __nv_bfloat16* __restrict__ Cl, int N, int K) {
    extern __shared__ __nv_bfloat16 sm[];
    __shared__ float s_bias[128];
    const int tid = threadIdx.x;
    const int lane = tid & 31, wid = tid >> 5;
    const int wm = wid >> 2, wn = wid & 3;
    const int m0 = blockIdx.y * 128, n0 = blockIdx.x * 128;
    const uint32_t smb = smem_u32(sm);

    if (tid < 128) s_bias[tid] = bias[n0 + tid];
    __syncthreads();

    const int crow = tid >> 1;
    const int ck = (tid & 1) * 16;
    const uint32_t srow = (uint32_t)(crow * PITCH + ck) * 2;

    const __nv_bfloat16* gAh = Ah + (size_t)(m0 + crow) * lda + ck;
    const __nv_bfloat16* gAl = Al + (size_t)(m0 + crow) * lda + ck;
    const __nv_bfloat16* gWh = Wh + (size_t)(n0 + crow) * ldb + ck;
    const __nv_bfloat16* gWl = Wl + (size_t)(n0 + crow) * ldb + ck;

    const int nk = K >> 5;

#pragma unroll
    for (int s = 0; s < STG - 1; ++s) {
        uint32_t sb = smb + (uint32_t)s * (ST_STRIDE * 2);
        int kk = s * 32;
        cp16(sb + ST_A_H * 2 + srow,      gAh + kk);
        cp16(sb + ST_A_H * 2 + srow + 16, gAh + kk + 8);
        cp16(sb + ST_A_L * 2 + srow,      gAl + kk);
        cp16(sb + ST_A_L * 2 + srow + 16, gAl + kk + 8);
        cp16(sb + ST_B_H * 2 + srow,      gWh + kk);
        cp16(sb + ST_B_H * 2 + srow + 16, gWh + kk + 8);
        cp16(sb + ST_B_L * 2 + srow,      gWl + kk);
        cp16(sb + ST_B_L * 2 + srow + 16, gWl + kk + 8);
        cp_commit();
    }

    float acc[4][4][4];
#pragma unroll
    for (int i = 0; i < 4; i++)
#pragma unroll
        for (int j = 0; j < 4; j++)
#pragma unroll
            for (int q = 0; q < 4; q++) acc[i][j][q] = 0.f;

    const int fr = lane & 15;
    const int fc = (lane >> 4) << 3;

    for (int t = 0; t < nk; ++t) {
        cp_wait<STG - 2>();
        __syncthreads();
        uint32_t sb = smb + (uint32_t)(t % STG) * (ST_STRIDE * 2);
#pragma unroll
        for (int ks = 0; ks < 2; ++ks) {
            uint32_t ah[4][4], al[4][4], bh[4][2], bl[4][2];
#pragma unroll
            for (int mt = 0; mt < 4; ++mt) {
                uint32_t a = sb + ST_A_H * 2 +
                             (uint32_t)((wm * 64 + mt * 16 + fr) * PITCH + ks * 16 + fc) * 2;
                ldsm4(ah[mt][0], ah[mt][1], ah[mt][2], ah[mt][3], a);
                ldsm4(al[mt][0], al[mt][1], al[mt][2], al[mt][3],
                      a + (ST_A_L - ST_A_H) * 2);
            }
#pragma unroll
            for (int pn = 0; pn < 2; ++pn) {
                uint32_t a = sb + ST_B_H * 2 +
                             (uint32_t)((wn * 32 + pn * 16 + fr) * PITCH + ks * 16 + fc) * 2;
                uint32_t r0, r1, r2, r3;
                ldsm4(r0, r1, r2, r3, a);
                bh[pn * 2][0] = r0; bh[pn * 2][1] = r2;
                bh[pn * 2 + 1][0] = r1; bh[pn * 2 + 1][1] = r3;
                ldsm4(r0, r1, r2, r3, a + (ST_B_L - ST_B_H) * 2);
                bl[pn * 2][0] = r0; bl[pn * 2][1] = r2;
                bl[pn * 2 + 1][0] = r1; bl[pn * 2 + 1][1] = r3;
            }
#pragma unroll
            for (int mt = 0; mt < 4; ++mt)
#pragma unroll
                for (int nt = 0; nt < 4; ++nt) {
                    mma16816(acc[mt][nt], ah[mt], bh[nt]);
                    mma16816(acc[mt][nt], ah[mt], bl[nt]);
                    mma16816(acc[mt][nt], al[mt], bh[nt]);
                }
        }
        __syncthreads();
        int tn = t + STG - 1;
        if (tn < nk) {
            uint32_t sb2 = smb + (uint32_t)(tn % STG) * (ST_STRIDE * 2);
            int kk = tn * 32;
            cp16(sb2 + ST_A_H * 2 + srow,      gAh + kk);
            cp16(sb2 + ST_A_H * 2 + srow + 16, gAh + kk + 8);
            cp16(sb2 + ST_A_L * 2 + srow,      gAl + kk);
            cp16(sb2 + ST_A_L * 2 + srow + 16, gAl + kk + 8);
            cp16(sb2 + ST_B_H * 2 + srow,      gWh + kk);
            cp16(sb2 + ST_B_H * 2 + srow + 16, gWh + kk + 8);
            cp16(sb2 + ST_B_L * 2 + srow,      gWl + kk);
            cp16(sb2 + ST_B_L * 2 + srow + 16, gWl + kk + 8);
            cp_commit();
        }
    }

    const int er = lane >> 2;
    const int ec = (lane & 3) * 2;
#pragma unroll
    for (int mt = 0; mt < 4; ++mt) {
#pragma unroll
        for (int nt = 0; nt < 4; ++nt) {
            int col = wn * 32 + nt * 8 + ec;
            float b0 = s_bias[col], b1 = s_bias[col + 1];
#pragma unroll
            for (int h = 0; h < 2; ++h) {
                int row = m0 + wm * 64 + mt * 16 + er + h * 8;
                size_t off = (size_t)row * N + n0 + col;
                float v0 = acc[mt][nt][h * 2 + 0] + b0;
                float v1 = acc[mt][nt][h * 2 + 1] + b1;
                if (ADDIN) {
                    float2 ci = *(const float2*)(Cin + off);
                    v0 += ci.x;
                    v1 += ci.y;
                }
                if (EPI == 1) { v0 = tanhf(v0); v1 = tanhf(v1); }
                if (WF32) *(float2*)(Cf + off) = make_float2(v0, v1);
                if (WSPLIT) {
                    __nv_bfloat16 h0, l0, h1, l1;
                    split2(v0, h0, l0);
                    split2(v1, h1, l1);
                    __nv_bfloat162 ph, pl;
                    ph.x = h0; ph.y = h1;
                    pl.x = l0; pl.y = l1;
                    *(__nv_bfloat162*)(Ch + off) = ph;
                    *(__nv_bfloat162*)(Cl + off) = pl;
                }
            }
        }
    }
}

// ---------------- FFMA SGEMM (fp32-exact) --------------------------------------------
#define BM 128
#define BN 128
#define BK 8

template <int EPI, int WC, int SPLITOUT>   // EPI 0:+bias 1:tanh 2:dist
__global__ void __launch_bounds__(256)
sgemm_kernel(const float* __restrict__ A, const float* __restrict__ B,
             const float* __restrict__ bias, const float* __restrict__ rown,
             float* __restrict__ C, __nv_bfloat16* __restrict__ Dh,
             __nv_bfloat16* __restrict__ Dl, int K, int ldb, int ldc) {
    __shared__ __align__(16) float As[2][BK][BM];
    __shared__ __align__(16) float Bs[2][BK][BN];
    const int tid = threadIdx.x;
    const int tx = tid & 15, ty = tid >> 4;
    const int m0 = blockIdx.y * BM, n0 = blockIdx.x * BN;
    const int arow = tid >> 1, akq = (tid & 1) * 4;
    const float* Aptr = A + (size_t)(m0 + arow) * K + akq;
    const int brow = tid >> 5, bcol = (tid & 31) * 4;
    const float* Bptr = B + (size_t)brow * ldb + n0 + bcol;
    float acc[8][8];
#pragma unroll
    for (int i = 0; i < 8; i++)
#pragma unroll
        for (int j = 0; j < 8; j++) acc[i][j] = 0.f;
    const int nt = K / BK;
    float4 a4 = *(const float4*)(Aptr);
    float4 b4 = *(const float4*)(Bptr);
    As[0][akq + 0][arow] = a4.x; As[0][akq + 1][arow] = a4.y;
    As[0][akq + 2][arow] = a4.z; As[0][akq + 3][arow] = a4.w;
    *(float4*)&Bs[0][brow][bcol] = b4;
    __syncthreads();
    int cur = 0;
    for (int t = 0; t < nt; t++) {
        if (t + 1 < nt) {
            a4 = *(const float4*)(Aptr + (t + 1) * BK);
            b4 = *(const float4*)(Bptr + (size_t)(t + 1) * BK * ldb);
        }
#pragma unroll
        for (int kk = 0; kk < BK; kk++) {
            float4 a0 = *(const float4*)&As[cur][kk][ty * 4];
            float4 a1 = *(const float4*)&As[cur][kk][64 + ty * 4];
            float4 b0 = *(const float4*)&Bs[cur][kk][tx * 4];
            float4 b1 = *(const float4*)&Bs[cur][kk][64 + tx * 4];
            float ar[8] = {a0.x, a0.y, a0.z, a0.w, a1.x, a1.y, a1.z, a1.w};
            float br[8] = {b0.x, b0.y, b0.z, b0.w, b1.x, b1.y, b1.z, b1.w};
#pragma unroll
            for (int i = 0; i < 8; i++)
#pragma unroll
                for (int j = 0; j < 8; j++) acc[i][j] = fmaf(ar[i], br[j], acc[i][j]);
        }
        if (t + 1 < nt) {
            int nx = cur ^ 1;
            As[nx][akq + 0][arow] = a4.x; As[nx][akq + 1][arow] = a4.y;
            As[nx][akq + 2][arow] = a4.z; As[nx][akq + 3][arow] = a4.w;
            *(float4*)&Bs[nx][brow][bcol] = b4;
        }
        __syncthreads();
        cur ^= 1;
    }
#pragma unroll
    for (int i = 0; i < 8; i++) {
        int r = m0 + ((i < 4) ? (ty * 4 + i) : (64 + ty * 4 + (i - 4)));
        float rn = (EPI == 2) ? rown[r] : 0.f;
#pragma unroll
        for (int jh = 0; jh < 2; jh++) {
            int c = n0 + jh * 64 + tx * 4;
            float4 bv = *(const float4*)(bias + c);
            const float* ap = &acc[i][jh * 4];
            float4 v;
            if (EPI == 2) {
                v.x = rn + bv.x - 2.f * ap[0];
                v.y = rn + bv.y - 2.f * ap[1];
                v.z = rn + bv.z - 2.f * ap[2];
                v.w = rn + bv.w - 2.f * ap[3];
            } else {
                v.x = ap[0] + bv.x; v.y = ap[1] + bv.y;
                v.z = ap[2] + bv.z; v.w = ap[3] + bv.w;
                if (EPI == 1) {
                    v.x = tanhf(v.x); v.y = tanhf(v.y);
                    v.z = tanhf(v.z); v.w = tanhf(v.w);
                }
            }
            size_t off = (size_t)r * ldc + c;
            if (WC) *(float4*)(C + off) = v;
            if (SPLITOUT) {
                __nv_bfloat16 h0, l0, h1, l1, h2, l2, h3, l3;
                split2(v.x, h0, l0); split2(v.y, h1, l1);
                split2(v.z, h2, l2); split2(v.w, h3, l3);
                __nv_bfloat162 ph0, ph1, pl0, pl1;
                ph0.x = h0; ph0.y = h1; ph1.x = h2; ph1.y = h3;
                pl0.x = l0; pl0.y = l1; pl1.x = l2; pl1.y = l3;
                *(__nv_bfloat162*)(Dh + off) = ph0;
                *(__nv_bfloat162*)(Dh + off + 2) = ph1;
                *(__nv_bfloat162*)(Dl + off) = pl0;
                *(__nv_bfloat162*)(Dl + off + 2) = pl1;
            }
        }
    }
}

// ---------------- small kernels --------------------------------------------------------
__global__ void prep_codebook_kernel(const float* __restrict__ cb) {
    int k = blockIdx.x;
    float s = 0.f;
    for (int d = threadIdx.x; d < OBS; d += blockDim.x) {
        float v = cb[(size_t)k * OBS + d];
        g_cbT[(size_t)d * KCB + k] = v;
        s += v * v;
    }
    s = blockReduceSum(s);
    if (threadIdx.x == 0) g_cnorm[k] = s;
}

__global__ void rownorm_kernel(const float* __restrict__ x) {
    int b = blockIdx.x;
    const float* r = x + (size_t)b * OBS;
    float s = 0.f;
    for (int d = threadIdx.x; d < OBS; d += blockDim.x) {
        float v = r[d];
        s += v * v;
    }
    s = blockReduceSum(s);
    if (threadIdx.x == 0) g_xnorm[b] = s;
}

__global__ void argmin_kernel(const float* __restrict__ dist, float* __restrict__ prop_out_f) {
    __shared__ float sv[256];
    __shared__ int si[256];
    int b = blockIdx.x;
    const float* r = dist + (size_t)b * KCB;
    float best = INFINITY;
    int bi = KCB;
    for (int k = threadIdx.x; k < KCB; k += 256) {
        float v = r[k];
        if (v < best) { best = v; bi = k; }
    }
    sv[threadIdx.x] = best;
    si[threadIdx.x] = bi;
    __syncthreads();
    for (int s = 128; s > 0; s >>= 1) {
        if (threadIdx.x < s) {
            float ov = sv[threadIdx.x + s];
            int oi = si[threadIdx.x + s];
            if (ov < sv[threadIdx.x] || (ov == sv[threadIdx.x] && oi < si[threadIdx.x])) {
                sv[threadIdx.x] = ov;
                si[threadIdx.x] = oi;
            }
        }
        __syncthreads();
    }
    if (threadIdx.x == 0) {
        g_prop[b] = si[0];
        prop_out_f[b] = (float)si[0];
    }
}

__global__ void xsplit_kernel(const float* __restrict__ X, __nv_bfloat16* __restrict__ xh,
                              __nv_bfloat16* __restrict__ xl) {
    size_t i = (size_t)blockIdx.x * blockDim.x + threadIdx.x;
    float v = X[i];
    __nv_bfloat16 h, l;
    split2(v, h, l);
    xh[i] = h;
    xl[i] = l;
}

__global__ void wsplit_kernel(const float* __restrict__ W, __nv_bfloat16* __restrict__ hi,
                              __nv_bfloat16* __restrict__ lo, int K, int N) {
    __shared__ float t[32][33];
    const int n0 = blockIdx.x * 32, k0 = blockIdx.y * 32;
    const int tx = threadIdx.x, ty = threadIdx.y;
#pragma unroll
    for (int i = 0; i < 4; i++)
        t[ty + i * 8][tx] = W[(size_t)(k0 + ty + i * 8) * N + n0 + tx];
    __syncthreads();
#pragma unroll
    for (int i = 0; i < 4; i++) {
        int n = ty + i * 8;
        float v = t[tx][n];
        __nv_bfloat16 h, l;
        split2(v, h, l);
        size_t o = (size_t)(n0 + n) * K + k0 + tx;
        hi[o] = h;
        lo[o] = l;
    }
}

__global__ void loss_partial_kernel(const float* __restrict__ dx, const float* __restrict__ cb) {
    const size_t NTOT = (size_t)BSZ * OBS;
    float s1 = 0.f, s2 = 0.f;
    for (size_t i = (size_t)blockIdx.x * blockDim.x + threadIdx.x; i < NTOT;
         i += (size_t)gridDim.x * blockDim.x) {
        int b = (int)(i >> 10);
        int d = (int)(i & 1023);
        size_t ko = (size_t)g_prop[b] * OBS + d;
        float a = dx[i] - g_cb_recon[ko];
        s1 += a * a;
        float c = g_enc[i] - cb[ko];
        s2 += c * c;
    }
    s1 = blockReduceSum(s1);
    __syncthreads();
    s2 = blockReduceSum(s2);
    if (threadIdx.x == 0) {
        g_part[2 * blockIdx.x + 0] = s1;
        g_part[2 * blockIdx.x + 1] = s2;
    }
}

__global__ void finalize_total_kernel(int nb, float* __restrict__ out_total) {
    float s1 = 0.f, s2 = 0.f;
    for (int i = threadIdx.x; i < nb; i += 256) {
        s1 += g_part[2 * i + 0];
        s2 += g_part[2 * i + 1];
    }
    s1 = blockReduceSum(s1);
    __syncthreads();
    s2 = blockReduceSum(s2);
    if (threadIdx.x == 0) {
        const float inv = 1.f / ((float)BSZ * (float)OBS);
        float tot = s1 * inv + 2.f * (s2 * inv);
        g_total[0] = tot;
        out_total[0] = tot;
    }
}

__global__ void policy_kernel(const float* __restrict__ A_, const float* __restrict__ log_std,
                              float* __restrict__ out_loss, float* __restrict__ out_losspi) {
    int b = blockIdx.x;
    int j = threadIdx.x;
    float ls = log_std[j];
    float sd = expf(ls);
    float z = (A_[(size_t)b * OUTD + j] - g_mu[(size_t)b * OUTD + j]) / sd;
    float logp = -0.5f * z * z - ls - 0.5f * LOG2PI_F;
    float term = 1.f / (expf(logp) + 0.1f);
    float lp = blockReduceSum(term);
    if (threadIdx.x == 0) {
        out_losspi[b] = lp;
        out_loss[b] = lp * g_total[0];
    }
}

// ---------------- launch ----------------------------------------------------------------
#define ENC_DUMMY_SMEM (100 * 1024)

extern "C" void kernel_launch(void* const* d_in, const int* in_sizes, int n_in,
                              void* d_out, int out_size) {
    const float* X        = (const float*)d_in[0];
    const float* Delta_X  = (const float*)d_in[1];
    const float* A        = (const float*)d_in[2];
    const float* enc_w1   = (const float*)d_in[3];
    const float* enc_b1   = (const float*)d_in[4];
    const float* enc_w2   = (const float*)d_in[5];
    const float* enc_b2   = (const float*)d_in[6];
    const float* prenet_w = (const float*)d_in[7];
    const float* prenet_b = (const float*)d_in[8];
    const float* codebook = (const float*)d_in[9];
    const float* postnet_w= (const float*)d_in[10];
    const float* postnet_b= (const float*)d_in[11];
    const float* dec_w1   = (const float*)d_in[12];
    const float* dec_b1   = (const float*)d_in[13];
    const float* dec_w2   = (const float*)d_in[14];
    const float* dec_b2   = (const float*)d_in[15];
    const float* dec_w3   = (const float*)d_in[16];
    const float* dec_b3   = (const float*)d_in[17];
    const float* act_w1   = (const float*)d_in[18];
    const float* act_b1   = (const float*)d_in[19];
    const float* act_w2   = (const float*)d_in[20];
    const float* act_b2   = (const float*)d_in[21];
    const float* act_w3   = (const float*)d_in[22];
    const float* act_b3   = (const float*)d_in[23];
    const float* log_std  = (const float*)d_in[24];

    float* out = (float*)d_out;
    float* out_loss   = out;
    float* out_losspi = out + BSZ;
    float* out_X      = out + 2 * (size_t)BSZ;
    float* out_prop   = out + 2 * (size_t)BSZ + (size_t)BSZ * OBS;
    float* out_total  = out_prop + BSZ;

    float *p_h1, *p_h2, *p_enc, *p_dist, *p_mu, *p_cbT, *p_cnorm, *p_xnorm, *p_zb, *p_p1;
    float *p_d0, *p_d1, *p_d2, *p_rec;
    __nv_bfloat16 *p_wh, *p_wl, *p_xh, *p_xl, *p_dh, *p_dl, *p_a1h, *p_a1l, *p_a2h, *p_a2l;
    cudaGetSymbolAddress((void**)&p_h1, g_h1);
    cudaGetSymbolAddress((void**)&p_h2, g_h2);
    cudaGetSymbolAddress((void**)&p_enc, g_enc);
    cudaGetSymbolAddress((void**)&p_dist, g_dist);
    cudaGetSymbolAddress((void**)&p_mu, g_mu);
    cudaGetSymbolAddress((void**)&p_cbT, g_cbT);
    cudaGetSymbolAddress((void**)&p_cnorm, g_cnorm);
    cudaGetSymbolAddress((void**)&p_xnorm, g_xnorm);
    cudaGetSymbolAddress((void**)&p_zb, g_zb);
    cudaGetSymbolAddress((void**)&p_p1, g_p1);
    cudaGetSymbolAddress((void**)&p_d0, g_cb_d0);
    cudaGetSymbolAddress((void**)&p_d1, g_cb_d1);
    cudaGetSymbolAddress((void**)&p_d2, g_cb_d2);
    cudaGetSymbolAddress((void**)&p_rec, g_cb_recon);
    cudaGetSymbolAddress((void**)&p_wh, g_wt_hi);
    cudaGetSymbolAddress((void**)&p_wl, g_wt_lo);
    cudaGetSymbolAddress((void**)&p_xh, g_xs_hi);
    cudaGetSymbolAddress((void**)&p_xl, g_xs_lo);
    cudaGetSymbolAddress((void**)&p_dh, g_ds_hi);
    cudaGetSymbolAddress((void**)&p_dl, g_ds_lo);
    cudaGetSymbolAddress((void**)&p_a1h, g_a1_hi);
    cudaGetSymbolAddress((void**)&p_a1l, g_a1_lo);
    cudaGetSymbolAddress((void**)&p_a2h, g_a2_hi);
    cudaGetSymbolAddress((void**)&p_a2l, g_a2_lo);

    // act1X: 2-stage, 128-reg cap (co-resident with encoder). Others: proven 3-stage.
    cudaFuncSetAttribute(mma_gemm<0, 1, 0, 0, 2, 2>, cudaFuncAttributeMaxDynamicSharedMemorySize, MMA_SMEM(2));
    cudaFuncSetAttribute(mma_gemm<1, 0, 1, 1, 3, 1>, cudaFuncAttributeMaxDynamicSharedMemorySize, MMA_SMEM(3));
    cudaFuncSetAttribute(mma_gemm<1, 0, 1, 0, 3, 1>, cudaFuncAttributeMaxDynamicSharedMemorySize, MMA_SMEM(3));
    cudaFuncSetAttribute(mma_gemm<0, 1, 0, 0, 3, 1>, cudaFuncAttributeMaxDynamicSharedMemorySize, MMA_SMEM(3));
    cudaFuncSetAttribute(sgemm_kernel<1, 1, 0>, cudaFuncAttributeMaxDynamicSharedMemorySize, ENC_DUMMY_SMEM);
    cudaFuncSetAttribute(sgemm_kernel<0, 1, 0>, cudaFuncAttributeMaxDynamicSharedMemorySize, ENC_DUMMY_SMEM);

    static cudaStream_t s2 = nullptr, s3 = nullptr;
    static cudaEvent_t evRoot = nullptr, evX = nullptr, evW = nullptr,
                       evArg = nullptr, evTot = nullptr, evS3 = nullptr;
    if (s2 == nullptr) {
        cudaStreamCreateWithFlags(&s2, cudaStreamNonBlocking);
        cudaStreamCreateWithFlags(&s3, cudaStreamNonBlocking);
        cudaEventCreateWithFlags(&evRoot, cudaEventDisableTiming);
        cudaEventCreateWithFlags(&evX, cudaEventDisableTiming);
        cudaEventCreateWithFlags(&evW, cudaEventDisableTiming);
        cudaEventCreateWithFlags(&evArg, cudaEventDisableTiming);
        cudaEventCreateWithFlags(&evTot, cudaEventDisableTiming);
        cudaEventCreateWithFlags(&evS3, cudaEventDisableTiming);
    }

    dim3 tb(32, 8);

    cudaEventRecord(evRoot, 0);
    cudaStreamWaitEvent(s2, evRoot, 0);

    // ---------- s2: X split + W1X split, then act1X (tensor, co-resident w/ encoder) ----
    xsplit_kernel<<<(BSZ * OBS) / 256, 256, 0, s2>>>(X, p_xh, p_xl);
    wsplit_kernel<<<dim3(2048 / 32, 1024 / 32), tb, 0, s2>>>(act_w1, p_wh + O_W1X, p_wl + O_W1X, 1024, 2048);
    mma_gemm<0, 1, 0, 0, 2, 2><<<dim3(16, 256), 256, MMA_SMEM(2), s2>>>(
        p_xh, p_xl, 1024, p_wh + O_W1X, p_wl + O_W1X, 1024, p_zb, nullptr,
        p_p1, nullptr, nullptr, 2048, 1024);
    cudaEventRecord(evX, s2);

    // ---------- main: encoder chain (fp32 FFMA, 1 CTA/SM via dummy smem) + dist + argmin
    prep_codebook_kernel<<<KCB, 256>>>(codebook);
    sgemm_kernel<1, 1, 0><<<dim3(512 / BN, BSZ / BM), 256, ENC_DUMMY_SMEM>>>(
        Delta_X, enc_w1, enc_b1, nullptr, p_h1, nullptr, nullptr, 1024, 512, 512);
    sgemm_kernel<1, 1, 0><<<dim3(1024 / BN, BSZ / BM), 256, ENC_DUMMY_SMEM>>>(
        p_h1, enc_w2, enc_b2, nullptr, p_h2, nullptr, nullptr, 512, 1024, 1024);
    sgemm_kernel<0, 1, 0><<<dim3(1024 / BN, BSZ / BM), 256, ENC_DUMMY_SMEM>>>(
        p_h2, prenet_w, prenet_b, nullptr, p_enc, nullptr, nullptr, 1024, 1024, 1024);
    rownorm_kernel<<<BSZ, 256>>>(p_enc);
    sgemm_kernel<2, 1, 1><<<dim3(KCB / BN, BSZ / BM), 256>>>(
        p_enc, p_cbT, p_cnorm, p_xnorm, p_dist, p_dh, p_dl, OBS, KCB, KCB);
    argmin_kernel<<<BSZ, 256>>>(p_dist, out_prop);
    cudaEventRecord(evArg, 0);

    // ---------- s3: actor weight splits + decoder-512 + out_X (after act1X frees SMs) ---
    cudaStreamWaitEvent(s3, evX, 0);
    wsplit_kernel<<<dim3(2048 / 32, 512 / 32), tb, 0, s3>>>(act_w1 + (size_t)1024 * 2048,
                                                            p_wh + O_W1D, p_wl + O_W1D, 512, 2048);
    wsplit_kernel<<<dim3(2048 / 32, 2048 / 32), tb, 0, s3>>>(act_w2, p_wh + O_W2, p_wl + O_W2, 2048, 2048);
    wsplit_kernel<<<dim3(256 / 32, 2048 / 32), tb, 0, s3>>>(act_w3, p_wh + O_A3, p_wl + O_A3, 2048, 256);
    cudaEventRecord(evW, s3);
    sgemm_kernel<1, 1, 0><<<dim3(1024 / BN, KCB / BM), 256, 0, s3>>>(codebook, postnet_w, postnet_b, nullptr, p_d0, nullptr, nullptr, 1024, 1024, 1024);
    sgemm_kernel<1, 1, 0><<<dim3(2048 / BN, KCB / BM), 256, 0, s3>>>(p_d0, dec_w1, dec_b1, nullptr, p_d1, nullptr, nullptr, 1024, 2048, 2048);
    sgemm_kernel<1, 1, 0><<<dim3(2048 / BN, KCB / BM), 256, 0, s3>>>(p_d1, dec_w2, dec_b2, nullptr, p_d2, nullptr, nullptr, 2048, 2048, 2048);
    sgemm_kernel<0, 1, 0><<<dim3(1024 / BN, KCB / BM), 256, 0, s3>>>(p_d2, dec_w3, dec_b3, nullptr, p_rec, nullptr, nullptr, 2048, 1024, 1024);
    cudaMemcpyAsync(out_X, X, (size_t)BSZ * OBS * sizeof(float), cudaMemcpyDeviceToDevice, s3);
    cudaEventRecord(evS3, s3);   // join point for s3 (consumed by s2 and main)

    // ---------- s2: VQ losses (after argmin AND after decoder/recon on s3) --------------
    cudaStreamWaitEvent(s2, evArg, 0);
    cudaStreamWaitEvent(s2, evS3, 0);
    loss_partial_kernel<<<2048, 256, 0, s2>>>(Delta_X, codebook);
    finalize_total_kernel<<<1, 256, 0, s2>>>(2048, out_total);
    cudaEventRecord(evTot, s2);

    // ---------- main: act1D (+p1, tanh, split), act2, act3 ----------
    cudaStreamWaitEvent(0, evX, 0);
    cudaStreamWaitEvent(0, evW, 0);
    mma_gemm<1, 0, 1, 1, 3, 1><<<dim3(16, 256), 256, MMA_SMEM(3)>>>(
        p_dh, p_dl, 512, p_wh + O_W1D, p_wl + O_W1D, 512, act_b1, p_p1,
        nullptr, p_a1h, p_a1l, 2048, 512);
    mma_gemm<1, 0, 1, 0, 3, 1><<<dim3(16, 256), 256, MMA_SMEM(3)>>>(
        p_a1h, p_a1l, 2048, p_wh + O_W2, p_wl + O_W2, 2048, act_b2, nullptr,
        nullptr, p_a2h, p_a2l, 2048, 2048);
    mma_gemm<0, 1, 0, 0, 3, 1><<<dim3(2, 256), 256, MMA_SMEM(3)>>>(
        p_a2h, p_a2l, 2048, p_wh + O_A3, p_wl + O_A3, 2048, act_b3, nullptr,
        p_mu, nullptr, nullptr, 256, 2048);

    // ---------- join everything into the origin stream ----------
    cudaStreamWaitEvent(0, evTot, 0);
    cudaStreamWaitEvent(0, evS3, 0);
    policy_kernel<<<BSZ, 256>>>(A, log_std, out_loss, out_losspi);
}

// round 14
// speedup vs baseline: 1.2188x; 1.2165x over previous
#include <cuda_runtime.h>
#include <cuda_fp16.h>
#include <math.h>
#include <stdint.h>

#define BSZ   32768
#define OBS   1024
#define OUTD  256
#define KCB   512
#define LOG2PI_F 1.83787706640934534f

// ---------------- fp32 scratch ---------------------------------------------------
__device__ float g_cbT[OBS * KCB];
__device__ float g_cnorm[KCB];
__device__ float g_xnorm[BSZ];
__device__ float g_h1[(size_t)BSZ * 512];
__device__ float g_h2[(size_t)BSZ * 1024];
__device__ float g_enc[(size_t)BSZ * 1024];
__device__ float g_dist[(size_t)BSZ * 512];
__device__ int   g_prop[BSZ];
__device__ float g_mu[(size_t)BSZ * 256];
__device__ float g_part[2048 * 2];
__device__ float g_total[1];
__device__ float g_zb[2048];                   // stays zero
__device__ float g_p1[(size_t)BSZ * 2048];     // act1 X-part partial (fp32)

// decoder computed on the 512 unique codebook rows only
__device__ float g_cb_d0[(size_t)KCB * 1024];
__device__ float g_cb_d1[(size_t)KCB * 2048];
__device__ float g_cb_d2[(size_t)KCB * 2048];
__device__ float g_cb_recon[(size_t)KCB * 1024];

// ---------------- fp16 arenas ------------------------------------------------------
__device__ __half g_xs_hi[(size_t)BSZ * 1024];
__device__ __half g_xs_lo[(size_t)BSZ * 1024];
__device__ __half g_ds_hi[(size_t)BSZ * 512];
__device__ __half g_ds_lo[(size_t)BSZ * 512];
__device__ __half g_a1[(size_t)BSZ * 2048];    // single fp16 (tanh output)
__device__ __half g_a2[(size_t)BSZ * 2048];    // single fp16 (tanh output)

// transposed + split actor weights [N][K] fp16 hi/lo
#define O_W1X   0u            // [2048][1024]
#define O_W1D   2097152u      // [2048][512]
#define O_W2    3145728u      // [2048][2048]
#define O_A3    7340032u      // [256][2048]
#define WT_TOTAL 7864320u
__device__ __half g_wt_hi[WT_TOTAL];
__device__ __half g_wt_lo[WT_TOTAL];

// ---------------- small helpers ----------------------------------------------------
__device__ __forceinline__ uint32_t smem_u32(const void* p) {
    uint32_t a;
    asm("{ .reg .u64 t; cvta.to.shared.u64 t, %1; cvt.u32.u64 %0, t; }" : "=r"(a) : "l"(p));
    return a;
}
__device__ __forceinline__ void cp16(uint32_t sdst, const void* gsrc) {
    uint64_t g;
    asm("cvta.to.global.u64 %0, %1;" : "=l"(g) : "l"(gsrc));
    asm volatile("cp.async.cg.shared.global [%0], [%1], 16;" :: "r"(sdst), "l"(g) : "memory");
}
__device__ __forceinline__ void cp_commit() {
    asm volatile("cp.async.commit_group;" ::: "memory");
}
template <int N>
__device__ __forceinline__ void cp_wait() {
    asm volatile("cp.async.wait_group %0;" :: "n"(N) : "memory");
}
__device__ __forceinline__ void ldsm4(uint32_t& r0, uint32_t& r1, uint32_t& r2, uint32_t& r3,
                                      uint32_t a) {
    asm volatile("ldmatrix.sync.aligned.m8n8.x4.shared.b16 {%0,%1,%2,%3}, [%4];"
                 : "=r"(r0), "=r"(r1), "=r"(r2), "=r"(r3) : "r"(a));
}
__device__ __forceinline__ void mma16816h(float* c, const uint32_t* a, const uint32_t* b) {
    asm volatile("mma.sync.aligned.m16n8k16.row.col.f32.f16.f16.f32 "
                 "{%0,%1,%2,%3}, {%4,%5,%6,%7}, {%8,%9}, {%0,%1,%2,%3};"
                 : "+f"(c[0]), "+f"(c[1]), "+f"(c[2]), "+f"(c[3])
                 : "r"(a[0]), "r"(a[1]), "r"(a[2]), "r"(a[3]), "r"(b[0]), "r"(b[1]));
}
__device__ __forceinline__ void split2h(float v, __half& h, __half& l) {
    h = __float2half(v);
    l = __float2half(v - __half2float(h));
}
__device__ __forceinline__ float blockReduceSum(float v) {
    __shared__ float sh[32];
    int lane = threadIdx.x & 31, wid = threadIdx.x >> 5;
#pragma unroll
    for (int o = 16; o > 0; o >>= 1) v += __shfl_down_sync(0xffffffffu, v, o);
    if (lane == 0) sh[wid] = v;
    __syncthreads();
    int nw = blockDim.x >> 5;
    v = (threadIdx.x < nw) ? sh[threadIdx.x] : 0.f;
    if (wid == 0) {
#pragma unroll
        for (int o = 16; o > 0; o >>= 1) v += __shfl_down_sync(0xffffffffu, v, o);
    }
    __syncthreads();
    return v;
}

#define PITCH 40

// ---------------- mma3: A hi/lo fp16 x W hi/lo fp16, 3 products ---------------------
#define S3_A_H 0
#define S3_A_L 5120
#define S3_B_H 10240
#define S3_B_L 15360
#define S3_STRIDE 20480
#define MMA3_SMEM (3 * S3_STRIDE * 2)

template <int EPI, int WF32, int WH16, int ADDIN>
__global__ void __launch_bounds__(256, 1)
mma3_gemm(const __half* __restrict__ Ah, const __half* __restrict__ Al, int lda,
          const __half* __restrict__ Wh, const __half* __restrict__ Wl, int ldb,
          const float* __restrict__ bias, const float* __restrict__ Cin,
          float* __restrict__ Cf, __half* __restrict__ Ch, int N, int K) {
    extern __shared__ __half sm[];
    __shared__ float s_bias[128];
    const int tid = threadIdx.x;
    const int lane = tid & 31, wid = tid >> 5;
    const int wm = wid >> 2, wn = wid & 3;
    const int m0 = blockIdx.y * 128, n0 = blockIdx.x * 128;
    const uint32_t smb = smem_u32(sm);

    if (tid < 128) s_bias[tid] = bias[n0 + tid];
    __syncthreads();

    const int crow = tid >> 1;
    const int ck = (tid & 1) * 16;
    const uint32_t srow = (uint32_t)(crow * PITCH + ck) * 2;
    const __half* gAh = Ah + (size_t)(m0 + crow) * lda + ck;
    const __half* gAl = Al + (size_t)(m0 + crow) * lda + ck;
    const __half* gWh = Wh + (size_t)(n0 + crow) * ldb + ck;
    const __half* gWl = Wl + (size_t)(n0 + crow) * ldb + ck;

    const int nk = K >> 5;

#define LD3(SBASE, KK)                                                  \
    do {                                                                \
        int kk = (KK);                                                  \
        cp16((SBASE) + S3_A_H * 2 + srow,      gAh + kk);               \
        cp16((SBASE) + S3_A_H * 2 + srow + 16, gAh + kk + 8);           \
        cp16((SBASE) + S3_A_L * 2 + srow,      gAl + kk);               \
        cp16((SBASE) + S3_A_L * 2 + srow + 16, gAl + kk + 8);           \
        cp16((SBASE) + S3_B_H * 2 + srow,      gWh + kk);               \
        cp16((SBASE) + S3_B_H * 2 + srow + 16, gWh + kk + 8);           \
        cp16((SBASE) + S3_B_L * 2 + srow,      gWl + kk);               \
        cp16((SBASE) + S3_B_L * 2 + srow + 16, gWl + kk + 8);           \
        cp_commit();                                                    \
    } while (0)

#pragma unroll
    for (int s = 0; s < 2; ++s) LD3(smb + (uint32_t)s * (S3_STRIDE * 2), s * 32);

    float acc[4][4][4];
#pragma unroll
    for (int i = 0; i < 4; i++)
#pragma unroll
        for (int j = 0; j < 4; j++)
#pragma unroll
            for (int q = 0; q < 4; q++) acc[i][j][q] = 0.f;

    const int fr = lane & 15;
    const int fc = (lane >> 4) << 3;

    for (int t = 0; t < nk; ++t) {
        cp_wait<1>();
        __syncthreads();
        uint32_t sb = smb + (uint32_t)(t % 3) * (S3_STRIDE * 2);
#pragma unroll
        for (int ks = 0; ks < 2; ++ks) {
            uint32_t ah[4][4], al[4][4], bh[4][2], bl[4][2];
#pragma unroll
            for (int mt = 0; mt < 4; ++mt) {
                uint32_t a = sb + S3_A_H * 2 +
                             (uint32_t)((wm * 64 + mt * 16 + fr) * PITCH + ks * 16 + fc) * 2;
                ldsm4(ah[mt][0], ah[mt][1], ah[mt][2], ah[mt][3], a);
                ldsm4(al[mt][0], al[mt][1], al[mt][2], al[mt][3],
                      a + (S3_A_L - S3_A_H) * 2);
            }
#pragma unroll
            for (int pn = 0; pn < 2; ++pn) {
                uint32_t a = sb + S3_B_H * 2 +
                             (uint32_t)((wn * 32 + pn * 16 + fr) * PITCH + ks * 16 + fc) * 2;
                uint32_t r0, r1, r2, r3;
                ldsm4(r0, r1, r2, r3, a);
                bh[pn * 2][0] = r0; bh[pn * 2][1] = r2;
                bh[pn * 2 + 1][0] = r1; bh[pn * 2 + 1][1] = r3;
                ldsm4(r0, r1, r2, r3, a + (S3_B_L - S3_B_H) * 2);
                bl[pn * 2][0] = r0; bl[pn * 2][1] = r2;
                bl[pn * 2 + 1][0] = r1; bl[pn * 2 + 1][1] = r3;
            }
#pragma unroll
            for (int mt = 0; mt < 4; ++mt)
#pragma unroll
                for (int nt = 0; nt < 4; ++nt) {
                    mma16816h(acc[mt][nt], ah[mt], bh[nt]);
                    mma16816h(acc[mt][nt], ah[mt], bl[nt]);
                    mma16816h(acc[mt][nt], al[mt], bh[nt]);
                }
        }
        __syncthreads();
        int tn = t + 2;
        if (tn < nk) LD3(smb + (uint32_t)(tn % 3) * (S3_STRIDE * 2), tn * 32);
    }
#undef LD3

    const int er = lane >> 2;
    const int ec = (lane & 3) * 2;
#pragma unroll
    for (int mt = 0; mt < 4; ++mt) {
#pragma unroll
        for (int nt = 0; nt < 4; ++nt) {
            int col = wn * 32 + nt * 8 + ec;
            float b0 = s_bias[col], b1 = s_bias[col + 1];
#pragma unroll
            for (int h = 0; h < 2; ++h) {
                int row = m0 + wm * 64 + mt * 16 + er + h * 8;
                size_t off = (size_t)row * N + n0 + col;
                float v0 = acc[mt][nt][h * 2 + 0] + b0;
                float v1 = acc[mt][nt][h * 2 + 1] + b1;
                if (ADDIN) {
                    float2 ci = *(const float2*)(Cin + off);
                    v0 += ci.x;
                    v1 += ci.y;
                }
                if (EPI == 1) { v0 = tanhf(v0); v1 = tanhf(v1); }
                if (WF32) *(float2*)(Cf + off) = make_float2(v0, v1);
                if (WH16) {
                    __half2 p;
                    p.x = __float2half(v0);
                    p.y = __float2half(v1);
                    *(__half2*)(Ch + off) = p;
                }
            }
        }
    }
}

// ---------------- mma2: A single fp16 x W hi/lo fp16, 2 products --------------------
#define S2_A  0
#define S2_WH 5120
#define S2_WL 10240
#define S2_STRIDE 15360
#define MMA2_SMEM (3 * S2_STRIDE * 2)

template <int EPI, int WF32, int WH16>
__global__ void __launch_bounds__(256, 1)
mma2_gemm(const __half* __restrict__ A, int lda,
          const __half* __restrict__ Wh, const __half* __restrict__ Wl, int ldb,
          const float* __restrict__ bias,
          float* __restrict__ Cf, __half* __restrict__ Ch, int N, int K) {
    extern __shared__ __half sm[];
    __shared__ float s_bias[128];
    const int tid = threadIdx.x;
    const int lane = tid & 31, wid = tid >> 5;
    const int wm = wid >> 2, wn = wid & 3;
    const int m0 = blockIdx.y * 128, n0 = blockIdx.x * 128;
    const uint32_t smb = smem_u32(sm);

    if (tid < 128) s_bias[tid] = bias[n0 + tid];
    __syncthreads();

    const int crow = tid >> 1;
    const int ck = (tid & 1) * 16;
    const uint32_t srow = (uint32_t)(crow * PITCH + ck) * 2;
    const __half* gA = A + (size_t)(m0 + crow) * lda + ck;
    const __half* gWh = Wh + (size_t)(n0 + crow) * ldb + ck;
    const __half* gWl = Wl + (size_t)(n0 + crow) * ldb + ck;

    const int nk = K >> 5;

#define LD2(SBASE, KK)                                                  \
    do {                                                                \
        int kk = (KK);                                                  \
        cp16((SBASE) + S2_A * 2 + srow,       gA + kk);                 \
        cp16((SBASE) + S2_A * 2 + srow + 16,  gA + kk + 8);             \
        cp16((SBASE) + S2_WH * 2 + srow,      gWh + kk);                \
        cp16((SBASE) + S2_WH * 2 + srow + 16, gWh + kk + 8);            \
        cp16((SBASE) + S2_WL * 2 + srow,      gWl + kk);                \
        cp16((SBASE) + S2_WL * 2 + srow + 16, gWl + kk + 8);            \
        cp_commit();                                                    \
    } while (0)

#pragma unroll
    for (int s = 0; s < 2; ++s) LD2(smb + (uint32_t)s * (S2_STRIDE * 2), s * 32);

    float acc[4][4][4];
#pragma unroll
    for (int i = 0; i < 4; i++)
#pragma unroll
        for (int j = 0; j < 4; j++)
#pragma unroll
            for (int q = 0; q < 4; q++) acc[i][j][q] = 0.f;

    const int fr = lane & 15;
    const int fc = (lane >> 4) << 3;

    for (int t = 0; t < nk; ++t) {
        cp_wait<1>();
        __syncthreads();
        uint32_t sb = smb + (uint32_t)(t % 3) * (S2_STRIDE * 2);
#pragma unroll
        for (int ks = 0; ks < 2; ++ks) {
            uint32_t af[4][4], bh[4][2], bl[4][2];
#pragma unroll
            for (int mt = 0; mt < 4; ++mt) {
                uint32_t a = sb + S2_A * 2 +
                             (uint32_t)((wm * 64 + mt * 16 + fr) * PITCH + ks * 16 + fc) * 2;
                ldsm4(af[mt][0], af[mt][1], af[mt][2], af[mt][3], a);
            }
#pragma unroll
            for (int pn = 0; pn < 2; ++pn) {
                uint32_t a = sb + S2_WH * 2 +
                             (uint32_t)((wn * 32 + pn * 16 + fr) * PITCH + ks * 16 + fc) * 2;
                uint32_t r0, r1, r2, r3;
                ldsm4(r0, r1, r2, r3, a);
                bh[pn * 2][0] = r0; bh[pn * 2][1] = r2;
                bh[pn * 2 + 1][0] = r1; bh[pn * 2 + 1][1] = r3;
                ldsm4(r0, r1, r2, r3, a + (S2_WL - S2_WH) * 2);
                bl[pn * 2][0] = r0; bl[pn * 2][1] = r2;
                bl[pn * 2 + 1][0] = r1; bl[pn * 2 + 1][1] = r3;
            }
#pragma unroll
            for (int mt = 0; mt < 4; ++mt)
#pragma unroll
                for (int nt = 0; nt < 4; ++nt) {
                    mma16816h(acc[mt][nt], af[mt], bh[nt]);
                    mma16816h(acc[mt][nt], af[mt], bl[nt]);
                }
        }
        __syncthreads();
        int tn = t + 2;
        if (tn < nk) LD2(smb + (uint32_t)(tn % 3) * (S2_STRIDE * 2), tn * 32);
    }
#undef LD2

    const int er = lane >> 2;
    const int ec = (lane & 3) * 2;
#pragma unroll
    for (int mt = 0; mt < 4; ++mt) {
#pragma unroll
        for (int nt = 0; nt < 4; ++nt) {
            int col = wn * 32 + nt * 8 + ec;
            float b0 = s_bias[col], b1 = s_bias[col + 1];
#pragma unroll
            for (int h = 0; h < 2; ++h) {
                int row = m0 + wm * 64 + mt * 16 + er + h * 8;
                size_t off = (size_t)row * N + n0 + col;
                float v0 = acc[mt][nt][h * 2 + 0] + b0;
                float v1 = acc[mt][nt][h * 2 + 1] + b1;
                if (EPI == 1) { v0 = tanhf(v0); v1 = tanhf(v1); }
                if (WF32) *(float2*)(Cf + off) = make_float2(v0, v1);
                if (WH16) {
                    __half2 p;
                    p.x = __float2half(v0);
                    p.y = __float2half(v1);
                    *(__half2*)(Ch + off) = p;
                }
            }
        }
    }
}

// ---------------- FFMA SGEMM (fp32-exact) --------------------------------------------
#define BM 128
#define BN 128
#define BK 8

template <int EPI, int WC, int SPLITOUT>   // EPI 0:+bias 1:tanh 2:dist
__global__ void __launch_bounds__(256)
sgemm_kernel(const float* __restrict__ A, const float* __restrict__ B,
             const float* __restrict__ bias, const float* __restrict__ rown,
             float* __restrict__ C, __half* __restrict__ Dh,
             __half* __restrict__ Dl, int K, int ldb, int ldc) {
    __shared__ __align__(16) float As[2][BK][BM];
    __shared__ __align__(16) float Bs[2][BK][BN];
    const int tid = threadIdx.x;
    const int tx = tid & 15, ty = tid >> 4;
    const int m0 = blockIdx.y * BM, n0 = blockIdx.x * BN;
    const int arow = tid >> 1, akq = (tid & 1) * 4;
    const float* Aptr = A + (size_t)(m0 + arow) * K + akq;
    const int brow = tid >> 5, bcol = (tid & 31) * 4;
    const float* Bptr = B + (size_t)brow * ldb + n0 + bcol;
    float acc[8][8];
#pragma unroll
    for (int i = 0; i < 8; i++)
#pragma unroll
        for (int j = 0; j < 8; j++) acc[i][j] = 0.f;
    const int nt = K / BK;
    float4 a4 = *(const float4*)(Aptr);
    float4 b4 = *(const float4*)(Bptr);
    As[0][akq + 0][arow] = a4.x; As[0][akq + 1][arow] = a4.y;
    As[0][akq + 2][arow] = a4.z; As[0][akq + 3][arow] = a4.w;
    *(float4*)&Bs[0][brow][bcol] = b4;
    __syncthreads();
    int cur = 0;
    for (int t = 0; t < nt; t++) {
        if (t + 1 < nt) {
            a4 = *(const float4*)(Aptr + (t + 1) * BK);
            b4 = *(const float4*)(Bptr + (size_t)(t + 1) * BK * ldb);
        }
#pragma unroll
        for (int kk = 0; kk < BK; kk++) {
            float4 a0 = *(const float4*)&As[cur][kk][ty * 4];
            float4 a1 = *(const float4*)&As[cur][kk][64 + ty * 4];
            float4 b0 = *(const float4*)&Bs[cur][kk][tx * 4];
            float4 b1 = *(const float4*)&Bs[cur][kk][64 + tx * 4];
            float ar[8] = {a0.x, a0.y, a0.z, a0.w, a1.x, a1.y, a1.z, a1.w};
            float br[8] = {b0.x, b0.y, b0.z, b0.w, b1.x, b1.y, b1.z, b1.w};
#pragma unroll
            for (int i = 0; i < 8; i++)
#pragma unroll
                for (int j = 0; j < 8; j++) acc[i][j] = fmaf(ar[i], br[j], acc[i][j]);
        }
        if (t + 1 < nt) {
            int nx = cur ^ 1;
            As[nx][akq + 0][arow] = a4.x; As[nx][akq + 1][arow] = a4.y;
            As[nx][akq + 2][arow] = a4.z; As[nx][akq + 3][arow] = a4.w;
            *(float4*)&Bs[nx][brow][bcol] = b4;
        }
        __syncthreads();
        cur ^= 1;
    }
#pragma unroll
    for (int i = 0; i < 8; i++) {
        int r = m0 + ((i < 4) ? (ty * 4 + i) : (64 + ty * 4 + (i - 4)));
        float rn = (EPI == 2) ? rown[r] : 0.f;
#pragma unroll
        for (int jh = 0; jh < 2; jh++) {
            int c = n0 + jh * 64 + tx * 4;
            float4 bv = *(const float4*)(bias + c);
            const float* ap = &acc[i][jh * 4];
            float4 v;
            if (EPI == 2) {
                v.x = rn + bv.x - 2.f * ap[0];
                v.y = rn + bv.y - 2.f * ap[1];
                v.z = rn + bv.z - 2.f * ap[2];
                v.w = rn + bv.w - 2.f * ap[3];
            } else {
                v.x = ap[0] + bv.x; v.y = ap[1] + bv.y;
                v.z = ap[2] + bv.z; v.w = ap[3] + bv.w;
                if (EPI == 1) {
                    v.x = tanhf(v.x); v.y = tanhf(v.y);
                    v.z = tanhf(v.z); v.w = tanhf(v.w);
                }
            }
            size_t off = (size_t)r * ldc + c;
            if (WC) *(float4*)(C + off) = v;
            if (SPLITOUT) {
                __half h0, l0, h1, l1, h2, l2, h3, l3;
                split2h(v.x, h0, l0); split2h(v.y, h1, l1);
                split2h(v.z, h2, l2); split2h(v.w, h3, l3);
                __half2 ph0, ph1, pl0, pl1;
                ph0.x = h0; ph0.y = h1; ph1.x = h2; ph1.y = h3;
                pl0.x = l0; pl0.y = l1; pl1.x = l2; pl1.y = l3;
                *(__half2*)(Dh + off) = ph0;
                *(__half2*)(Dh + off + 2) = ph1;
                *(__half2*)(Dl + off) = pl0;
                *(__half2*)(Dl + off + 2) = pl1;
            }
        }
    }
}

// ---------------- small kernels --------------------------------------------------------
__global__ void prep_codebook_kernel(const float* __restrict__ cb) {
    int k = blockIdx.x;
    float s = 0.f;
    for (int d = threadIdx.x; d < OBS; d += blockDim.x) {
        float v = cb[(size_t)k * OBS + d];
        g_cbT[(size_t)d * KCB + k] = v;
        s += v * v;
    }
    s = blockReduceSum(s);
    if (threadIdx.x == 0) g_cnorm[k] = s;
}

__global__ void rownorm_kernel(const float* __restrict__ x) {
    int b = blockIdx.x;
    const float* r = x + (size_t)b * OBS;
    float s = 0.f;
    for (int d = threadIdx.x; d < OBS; d += blockDim.x) {
        float v = r[d];
        s += v * v;
    }
    s = blockReduceSum(s);
    if (threadIdx.x == 0) g_xnorm[b] = s;
}

__global__ void argmin_kernel(const float* __restrict__ dist, float* __restrict__ prop_out_f) {
    __shared__ float sv[256];
    __shared__ int si[256];
    int b = blockIdx.x;
    const float* r = dist + (size_t)b * KCB;
    float best = INFINITY;
    int bi = KCB;
    for (int k = threadIdx.x; k < KCB; k += 256) {
        float v = r[k];
        if (v < best) { best = v; bi = k; }
    }
    sv[threadIdx.x] = best;
    si[threadIdx.x] = bi;
    __syncthreads();
    for (int s = 128; s > 0; s >>= 1) {
        if (threadIdx.x < s) {
            float ov = sv[threadIdx.x + s];
            int oi = si[threadIdx.x + s];
            if (ov < sv[threadIdx.x] || (ov == sv[threadIdx.x] && oi < si[threadIdx.x])) {
                sv[threadIdx.x] = ov;
                si[threadIdx.x] = oi;
            }
        }
        __syncthreads();
    }
    if (threadIdx.x == 0) {
        g_prop[b] = si[0];
        prop_out_f[b] = (float)si[0];
    }
}

__global__ void xsplit_kernel(const float* __restrict__ X, __half* __restrict__ xh,
                              __half* __restrict__ xl) {
    size_t i = (size_t)blockIdx.x * blockDim.x + threadIdx.x;
    float v = X[i];
    __half h, l;
    split2h(v, h, l);
    xh[i] = h;
    xl[i] = l;
}

// transpose+split: W[K,N] f32 -> [N,K] fp16 hi/lo
__global__ void wsplit_kernel(const float* __restrict__ W, __half* __restrict__ hi,
                              __half* __restrict__ lo, int K, int N) {
    __shared__ float t[32][33];
    const int n0 = blockIdx.x * 32, k0 = blockIdx.y * 32;
    const int tx = threadIdx.x, ty = threadIdx.y;
#pragma unroll
    for (int i = 0; i < 4; i++)
        t[ty + i * 8][tx] = W[(size_t)(k0 + ty + i * 8) * N + n0 + tx];
    __syncthreads();
#pragma unroll
    for (int i = 0; i < 4; i++) {
        int n = ty + i * 8;
        float v = t[tx][n];
        __half h, l;
        split2h(v, h, l);
        size_t o = (size_t)(n0 + n) * K + k0 + tx;
        hi[o] = h;
        lo[o] = l;
    }
}

__global__ void loss_partial_kernel(const float* __restrict__ dx, const float* __restrict__ cb) {
    const size_t NTOT = (size_t)BSZ * OBS;
    float s1 = 0.f, s2 = 0.f;
    for (size_t i = (size_t)blockIdx.x * blockDim.x + threadIdx.x; i < NTOT;
         i += (size_t)gridDim.x * blockDim.x) {
        int b = (int)(i >> 10);
        int d = (int)(i & 1023);
        size_t ko = (size_t)g_prop[b] * OBS + d;
        float a = dx[i] - g_cb_recon[ko];
        s1 += a * a;
        float c = g_enc[i] - cb[ko];
        s2 += c * c;
    }
    s1 = blockReduceSum(s1);
    __syncthreads();
    s2 = blockReduceSum(s2);
    if (threadIdx.x == 0) {
        g_part[2 * blockIdx.x + 0] = s1;
        g_part[2 * blockIdx.x + 1] = s2;
    }
}

__global__ void finalize_total_kernel(int nb, float* __restrict__ out_total) {
    float s1 = 0.f, s2 = 0.f;
    for (int i = threadIdx.x; i < nb; i += 256) {
        s1 += g_part[2 * i + 0];
        s2 += g_part[2 * i + 1];
    }
    s1 = blockReduceSum(s1);
    __syncthreads();
    s2 = blockReduceSum(s2);
    if (threadIdx.x == 0) {
        const float inv = 1.f / ((float)BSZ * (float)OBS);
        float tot = s1 * inv + 2.f * (s2 * inv);
        g_total[0] = tot;
        out_total[0] = tot;
    }
}

__global__ void policy_kernel(const float* __restrict__ A_, const float* __restrict__ log_std,
                              float* __restrict__ out_loss, float* __restrict__ out_losspi) {
    int b = blockIdx.x;
    int j = threadIdx.x;
    float ls = log_std[j];
    float sd = expf(ls);
    float z = (A_[(size_t)b * OUTD + j] - g_mu[(size_t)b * OUTD + j]) / sd;
    float logp = -0.5f * z * z - ls - 0.5f * LOG2PI_F;
    float term = 1.f / (expf(logp) + 0.1f);
    float lp = blockReduceSum(term);
    if (threadIdx.x == 0) {
        out_losspi[b] = lp;
        out_loss[b] = lp * g_total[0];
    }
}

// ---------------- launch ----------------------------------------------------------------
extern "C" void kernel_launch(void* const* d_in, const int* in_sizes, int n_in,
                              void* d_out, int out_size) {
    const float* X        = (const float*)d_in[0];
    const float* Delta_X  = (const float*)d_in[1];
    const float* A        = (const float*)d_in[2];
    const float* enc_w1   = (const float*)d_in[3];
    const float* enc_b1   = (const float*)d_in[4];
    const float* enc_w2   = (const float*)d_in[5];
    const float* enc_b2   = (const float*)d_in[6];
    const float* prenet_w = (const float*)d_in[7];
    const float* prenet_b = (const float*)d_in[8];
    const float* codebook = (const float*)d_in[9];
    const float* postnet_w= (const float*)d_in[10];
    const float* postnet_b= (const float*)d_in[11];
    const float* dec_w1   = (const float*)d_in[12];
    const float* dec_b1   = (const float*)d_in[13];
    const float* dec_w2   = (const float*)d_in[14];
    const float* dec_b2   = (const float*)d_in[15];
    const float* dec_w3   = (const float*)d_in[16];
    const float* dec_b3   = (const float*)d_in[17];
    const float* act_w1   = (const float*)d_in[18];
    const float* act_b1   = (const float*)d_in[19];
    const float* act_w2   = (const float*)d_in[20];
    const float* act_b2   = (const float*)d_in[21];
    const float* act_w3   = (const float*)d_in[22];
    const float* act_b3   = (const float*)d_in[23];
    const float* log_std  = (const float*)d_in[24];

    float* out = (float*)d_out;
    float* out_loss   = out;
    float* out_losspi = out + BSZ;
    float* out_X      = out + 2 * (size_t)BSZ;
    float* out_prop   = out + 2 * (size_t)BSZ + (size_t)BSZ * OBS;
    float* out_total  = out_prop + BSZ;

    float *p_h1, *p_h2, *p_enc, *p_dist, *p_mu, *p_cbT, *p_cnorm, *p_xnorm, *p_zb, *p_p1;
    float *p_d0, *p_d1, *p_d2, *p_rec;
    __half *p_wh, *p_wl, *p_xh, *p_xl, *p_dh, *p_dl, *p_a1, *p_a2;
    cudaGetSymbolAddress((void**)&p_h1, g_h1);
    cudaGetSymbolAddress((void**)&p_h2, g_h2);
    cudaGetSymbolAddress((void**)&p_enc, g_enc);
    cudaGetSymbolAddress((void**)&p_dist, g_dist);
    cudaGetSymbolAddress((void**)&p_mu, g_mu);
    cudaGetSymbolAddress((void**)&p_cbT, g_cbT);
    cudaGetSymbolAddress((void**)&p_cnorm, g_cnorm);
    cudaGetSymbolAddress((void**)&p_xnorm, g_xnorm);
    cudaGetSymbolAddress((void**)&p_zb, g_zb);
    cudaGetSymbolAddress((void**)&p_p1, g_p1);
    cudaGetSymbolAddress((void**)&p_d0, g_cb_d0);
    cudaGetSymbolAddress((void**)&p_d1, g_cb_d1);
    cudaGetSymbolAddress((void**)&p_d2, g_cb_d2);
    cudaGetSymbolAddress((void**)&p_rec, g_cb_recon);
    cudaGetSymbolAddress((void**)&p_wh, g_wt_hi);
    cudaGetSymbolAddress((void**)&p_wl, g_wt_lo);
    cudaGetSymbolAddress((void**)&p_xh, g_xs_hi);
    cudaGetSymbolAddress((void**)&p_xl, g_xs_lo);
    cudaGetSymbolAddress((void**)&p_dh, g_ds_hi);
    cudaGetSymbolAddress((void**)&p_dl, g_ds_lo);
    cudaGetSymbolAddress((void**)&p_a1, g_a1);
    cudaGetSymbolAddress((void**)&p_a2, g_a2);

    cudaFuncSetAttribute(mma3_gemm<0, 1, 0, 0>, cudaFuncAttributeMaxDynamicSharedMemorySize, MMA3_SMEM);
    cudaFuncSetAttribute(mma3_gemm<1, 0, 1, 1>, cudaFuncAttributeMaxDynamicSharedMemorySize, MMA3_SMEM);
    cudaFuncSetAttribute(mma2_gemm<1, 0, 1>, cudaFuncAttributeMaxDynamicSharedMemorySize, MMA2_SMEM);
    cudaFuncSetAttribute(mma2_gemm<0, 1, 0>, cudaFuncAttributeMaxDynamicSharedMemorySize, MMA2_SMEM);

    static cudaStream_t s2 = nullptr;
    static cudaEvent_t evRoot = nullptr, evW = nullptr, evArg = nullptr, evTot = nullptr;
    if (s2 == nullptr) {
        cudaStreamCreateWithFlags(&s2, cudaStreamNonBlocking);
        cudaEventCreateWithFlags(&evRoot, cudaEventDisableTiming);
        cudaEventCreateWithFlags(&evW, cudaEventDisableTiming);
        cudaEventCreateWithFlags(&evArg, cudaEventDisableTiming);
        cudaEventCreateWithFlags(&evTot, cudaEventDisableTiming);
    }

    dim3 tb(32, 8);

    cudaEventRecord(evRoot, 0);
    cudaStreamWaitEvent(s2, evRoot, 0);

    // ---------- s2 (block A): splits, decoder-512, out_X ----------
    xsplit_kernel<<<(BSZ * OBS) / 256, 256, 0, s2>>>(X, p_xh, p_xl);
    wsplit_kernel<<<dim3(2048 / 32, 1024 / 32), tb, 0, s2>>>(act_w1, p_wh + O_W1X, p_wl + O_W1X, 1024, 2048);
    wsplit_kernel<<<dim3(2048 / 32, 512 / 32), tb, 0, s2>>>(act_w1 + (size_t)1024 * 2048,
                                                            p_wh + O_W1D, p_wl + O_W1D, 512, 2048);
    wsplit_kernel<<<dim3(2048 / 32, 2048 / 32), tb, 0, s2>>>(act_w2, p_wh + O_W2, p_wl + O_W2, 2048, 2048);
    wsplit_kernel<<<dim3(256 / 32, 2048 / 32), tb, 0, s2>>>(act_w3, p_wh + O_A3, p_wl + O_A3, 2048, 256);
    cudaEventRecord(evW, s2);
    sgemm_kernel<1, 1, 0><<<dim3(1024 / BN, KCB / BM), 256, 0, s2>>>(codebook, postnet_w, postnet_b, nullptr, p_d0, nullptr, nullptr, 1024, 1024, 1024);
    sgemm_kernel<1, 1, 0><<<dim3(2048 / BN, KCB / BM), 256, 0, s2>>>(p_d0, dec_w1, dec_b1, nullptr, p_d1, nullptr, nullptr, 1024, 2048, 2048);
    sgemm_kernel<1, 1, 0><<<dim3(2048 / BN, KCB / BM), 256, 0, s2>>>(p_d1, dec_w2, dec_b2, nullptr, p_d2, nullptr, nullptr, 2048, 2048, 2048);
    sgemm_kernel<0, 1, 0><<<dim3(1024 / BN, KCB / BM), 256, 0, s2>>>(p_d2, dec_w3, dec_b3, nullptr, p_rec, nullptr, nullptr, 2048, 1024, 1024);
    cudaMemcpyAsync(out_X, X, (size_t)BSZ * OBS * sizeof(float), cudaMemcpyDeviceToDevice, s2);

    // ---------- main: encoder (fp32) + distances + argmin ----------
    prep_codebook_kernel<<<KCB, 256>>>(codebook);
    sgemm_kernel<1, 1, 0><<<dim3(512 / BN, BSZ / BM), 256>>>(Delta_X, enc_w1, enc_b1, nullptr, p_h1, nullptr, nullptr, 1024, 512, 512);
    sgemm_kernel<1, 1, 0><<<dim3(1024 / BN, BSZ / BM), 256>>>(p_h1, enc_w2, enc_b2, nullptr, p_h2, nullptr, nullptr, 512, 1024, 1024);
    sgemm_kernel<0, 1, 0><<<dim3(1024 / BN, BSZ / BM), 256>>>(p_h2, prenet_w, prenet_b, nullptr, p_enc, nullptr, nullptr, 1024, 1024, 1024);
    rownorm_kernel<<<BSZ, 256>>>(p_enc);
    sgemm_kernel<2, 1, 1><<<dim3(KCB / BN, BSZ / BM), 256>>>(p_enc, p_cbT, p_cnorm, p_xnorm, p_dist, p_dh, p_dl, OBS, KCB, KCB);
    argmin_kernel<<<BSZ, 256>>>(p_dist, out_prop);
    cudaEventRecord(evArg, 0);   // recorded BEFORE any wait on it (capture-legal)

    // ---------- s2 (block B): VQ losses, after argmin (event already recorded) ----------
    cudaStreamWaitEvent(s2, evArg, 0);
    loss_partial_kernel<<<2048, 256, 0, s2>>>(Delta_X, codebook);
    finalize_total_kernel<<<1, 256, 0, s2>>>(2048, out_total);
    cudaEventRecord(evTot, s2);

    // ---------- main: actor (fp16 tensor cores) ----------
    cudaStreamWaitEvent(0, evW, 0);
    // act1X: p1 = X @ W1x (3-product fp16)
    mma3_gemm<0, 1, 0, 0><<<dim3(16, 256), 256, MMA3_SMEM>>>(
        p_xh, p_xl, 1024, p_wh + O_W1X, p_wl + O_W1X, 1024, p_zb, nullptr,
        p_p1, nullptr, 2048, 1024);
    // act1D: a1 = tanh(p1 + dist @ W1d + b1) -> fp16
    mma3_gemm<1, 0, 1, 1><<<dim3(16, 256), 256, MMA3_SMEM>>>(
        p_dh, p_dl, 512, p_wh + O_W1D, p_wl + O_W1D, 512, act_b1, p_p1,
        nullptr, p_a1, 2048, 512);
    // act2: a2 = tanh(a1 @ W2 + b2), A single fp16 (2 products)
    mma2_gemm<1, 0, 1><<<dim3(16, 256), 256, MMA2_SMEM>>>(
        p_a1, 2048, p_wh + O_W2, p_wl + O_W2, 2048, act_b2,
        nullptr, p_a2, 2048, 2048);
    // act3: mu = a2 @ W3 + b3
    mma2_gemm<0, 1, 0><<<dim3(2, 256), 256, MMA2_SMEM>>>(
        p_a2, 2048, p_wh + O_A3, p_wl + O_A3, 2048, act_b3,
        p_mu, nullptr, 256, 2048);

    cudaStreamWaitEvent(0, evTot, 0);
    policy_kernel<<<BSZ, 256>>>(A, log_std, out_loss, out_losspi);
}

// round 16
// speedup vs baseline: 1.7128x; 1.4052x over previous
#include <cuda_runtime.h>
#include <cuda_fp16.h>
#include <math.h>
#include <stdint.h>

#define BSZ   32768
#define OBS   1024
#define OUTD  256
#define KCB   512
#define LOG2PI_F 1.83787706640934534f

// ---------------- fp32 scratch ---------------------------------------------------
__device__ float g_cbT[OBS * KCB];
__device__ float g_cnorm[KCB];
__device__ float g_xnorm[BSZ];
__device__ float g_h1[(size_t)BSZ * 512];
__device__ float g_h2[(size_t)BSZ * 1024];
__device__ float g_enc[(size_t)BSZ * 1024];
__device__ float g_dist[(size_t)BSZ * 512];
__device__ int   g_prop[BSZ];
__device__ float g_mu[(size_t)BSZ * 256];
__device__ float g_part[2048 * 2];
__device__ float g_total[1];
__device__ float g_u1[2048];                   // colsum of W1 dist-part (fp32)

// decoder computed on the 512 unique codebook rows only
__device__ float g_cb_d0[(size_t)KCB * 1024];
__device__ float g_cb_d1[(size_t)KCB * 2048];
__device__ float g_cb_d2[(size_t)KCB * 2048];
__device__ float g_cb_recon[(size_t)KCB * 1024];

// ---------------- fp16 arenas ------------------------------------------------------
__device__ __half g_xs[(size_t)BSZ * 1024];    // X fp16
__device__ __half g_dc[(size_t)BSZ * 512];     // centered dist d' = cnorm - 2 x.e (fp16)
__device__ __half g_a1[(size_t)BSZ * 2048];
__device__ __half g_a2[(size_t)BSZ * 2048];

// transposed single-fp16 actor weights [N][K]
#define O_W1    0u            // [2048][1536]  ([W1x | W1d] per row)
#define O_W2    3145728u      // [2048][2048]
#define O_A3    7340032u      // [256][2048]
#define WT_TOTAL 7864320u
__device__ __half g_wt[WT_TOTAL];

// ---------------- small helpers ----------------------------------------------------
__device__ __forceinline__ uint32_t smem_u32(const void* p) {
    uint32_t a;
    asm("{ .reg .u64 t; cvta.to.shared.u64 t, %1; cvt.u32.u64 %0, t; }" : "=r"(a) : "l"(p));
    return a;
}
__device__ __forceinline__ void cp16(uint32_t sdst, const void* gsrc) {
    uint64_t g;
    asm("cvta.to.global.u64 %0, %1;" : "=l"(g) : "l"(gsrc));
    asm volatile("cp.async.cg.shared.global [%0], [%1], 16;" :: "r"(sdst), "l"(g) : "memory");
}
__device__ __forceinline__ void cp_commit() {
    asm volatile("cp.async.commit_group;" ::: "memory");
}
template <int N>
__device__ __forceinline__ void cp_wait() {
    asm volatile("cp.async.wait_group %0;" :: "n"(N) : "memory");
}
__device__ __forceinline__ void ldsm4(uint32_t& r0, uint32_t& r1, uint32_t& r2, uint32_t& r3,
                                      uint32_t a) {
    asm volatile("ldmatrix.sync.aligned.m8n8.x4.shared.b16 {%0,%1,%2,%3}, [%4];"
                 : "=r"(r0), "=r"(r1), "=r"(r2), "=r"(r3) : "r"(a));
}
__device__ __forceinline__ void mma16816h(float* c, const uint32_t* a, const uint32_t* b) {
    asm volatile("mma.sync.aligned.m16n8k16.row.col.f32.f16.f16.f32 "
                 "{%0,%1,%2,%3}, {%4,%5,%6,%7}, {%8,%9}, {%0,%1,%2,%3};"
                 : "+f"(c[0]), "+f"(c[1]), "+f"(c[2]), "+f"(c[3])
                 : "r"(a[0]), "r"(a[1]), "r"(a[2]), "r"(a[3]), "r"(b[0]), "r"(b[1]));
}
__device__ __forceinline__ float blockReduceSum(float v) {
    __shared__ float sh[32];
    int lane = threadIdx.x & 31, wid = threadIdx.x >> 5;
#pragma unroll
    for (int o = 16; o > 0; o >>= 1) v += __shfl_down_sync(0xffffffffu, v, o);
    if (lane == 0) sh[wid] = v;
    __syncthreads();
    int nw = blockDim.x >> 5;
    v = (threadIdx.x < nw) ? sh[threadIdx.x] : 0.f;
    if (wid == 0) {
#pragma unroll
        for (int o = 16; o > 0; o >>= 1) v += __shfl_down_sync(0xffffffffu, v, o);
    }
    __syncthreads();
    return v;
}

#define PITCH 40

// ---------------- mma1: A fp16 x W fp16, single product ----------------------------
// EPI 0: acc+bias -> fp32.  EPI 1: tanh(acc+bias[+xnorm*u]) -> fp16.
// CONCAT: A = [A (lda 1024) | A2 (lda 512)], K=1536.  UCORR: add xnorm[row]*u[col].
#define S1_A  0
#define S1_W  5120
#define S1_STRIDE 10240
#define MMA1_SMEM (3 * S1_STRIDE * 2)

template <int EPI, int WF32, int WH16, int CONCAT, int UCORR>
__global__ void __launch_bounds__(256, 1)
mma1_gemm(const __half* __restrict__ A, const __half* __restrict__ A2, int lda,
          const __half* __restrict__ W, int ldb,
          const float* __restrict__ bias,
          float* __restrict__ Cf, __half* __restrict__ Ch, int N, int K) {
    extern __shared__ __half sm[];
    __shared__ float s_bias[128];
    __shared__ float s_u[128];
    const int tid = threadIdx.x;
    const int lane = tid & 31, wid = tid >> 5;
    const int wm = wid >> 2, wn = wid & 3;
    const int m0 = blockIdx.y * 128, n0 = blockIdx.x * 128;
    const uint32_t smb = smem_u32(sm);

    if (tid < 128) {
        s_bias[tid] = bias[n0 + tid];
        if (UCORR) s_u[tid] = g_u1[n0 + tid];
    }
    __syncthreads();

    const int crow = tid >> 1;
    const int ck = (tid & 1) * 16;
    const uint32_t srow = (uint32_t)(crow * PITCH + ck) * 2;

    const int nk = K >> 5;

#define LD1(SBASE, KK)                                                             \
    do {                                                                           \
        int k0 = (KK) + ck;                                                        \
        const __half *pa0, *pa1;                                                   \
        if (CONCAT && k0 >= 1024)                                                  \
            pa0 = A2 + (size_t)(m0 + crow) * 512 + (k0 - 1024);                    \
        else                                                                       \
            pa0 = A + (size_t)(m0 + crow) * lda + k0;                              \
        if (CONCAT && k0 + 8 >= 1024)                                              \
            pa1 = A2 + (size_t)(m0 + crow) * 512 + (k0 + 8 - 1024);                \
        else                                                                       \
            pa1 = A + (size_t)(m0 + crow) * lda + k0 + 8;                          \
        const __half* pb = W + (size_t)(n0 + crow) * ldb + k0;                     \
        cp16((SBASE) + S1_A * 2 + srow,      pa0);                                 \
        cp16((SBASE) + S1_A * 2 + srow + 16, pa1);                                 \
        cp16((SBASE) + S1_W * 2 + srow,      pb);                                  \
        cp16((SBASE) + S1_W * 2 + srow + 16, pb + 8);                              \
        cp_commit();                                                               \
    } while (0)

#pragma unroll
    for (int s = 0; s < 2; ++s) LD1(smb + (uint32_t)s * (S1_STRIDE * 2), s * 32);

    float acc[4][4][4];
#pragma unroll
    for (int i = 0; i < 4; i++)
#pragma unroll
        for (int j = 0; j < 4; j++)
#pragma unroll
            for (int q = 0; q < 4; q++) acc[i][j][q] = 0.f;

    const int fr = lane & 15;
    const int fc = (lane >> 4) << 3;

    for (int t = 0; t < nk; ++t) {
        cp_wait<1>();
        __syncthreads();
        uint32_t sb = smb + (uint32_t)(t % 3) * (S1_STRIDE * 2);
#pragma unroll
        for (int ks = 0; ks < 2; ++ks) {
            uint32_t af[4][4], bf[4][2];
#pragma unroll
            for (int mt = 0; mt < 4; ++mt) {
                uint32_t a = sb + S1_A * 2 +
                             (uint32_t)((wm * 64 + mt * 16 + fr) * PITCH + ks * 16 + fc) * 2;
                ldsm4(af[mt][0], af[mt][1], af[mt][2], af[mt][3], a);
            }
#pragma unroll
            for (int pn = 0; pn < 2; ++pn) {
                uint32_t a = sb + S1_W * 2 +
                             (uint32_t)((wn * 32 + pn * 16 + fr) * PITCH + ks * 16 + fc) * 2;
                uint32_t r0, r1, r2, r3;
                ldsm4(r0, r1, r2, r3, a);
                bf[pn * 2][0] = r0; bf[pn * 2][1] = r2;
                bf[pn * 2 + 1][0] = r1; bf[pn * 2 + 1][1] = r3;
            }
#pragma unroll
            for (int mt = 0; mt < 4; ++mt)
#pragma unroll
                for (int nt = 0; nt < 4; ++nt)
                    mma16816h(acc[mt][nt], af[mt], bf[nt]);
        }
        __syncthreads();
        int tn = t + 2;
        if (tn < nk) LD1(smb + (uint32_t)(tn % 3) * (S1_STRIDE * 2), tn * 32);
    }
#undef LD1

    const int er = lane >> 2;
    const int ec = (lane & 3) * 2;
#pragma unroll
    for (int mt = 0; mt < 4; ++mt) {
#pragma unroll
        for (int nt = 0; nt < 4; ++nt) {
            int col = wn * 32 + nt * 8 + ec;
            float b0 = s_bias[col], b1 = s_bias[col + 1];
#pragma unroll
            for (int h = 0; h < 2; ++h) {
                int row = m0 + wm * 64 + mt * 16 + er + h * 8;
                size_t off = (size_t)row * N + n0 + col;
                float v0 = acc[mt][nt][h * 2 + 0] + b0;
                float v1 = acc[mt][nt][h * 2 + 1] + b1;
                if (UCORR) {
                    float xn = g_xnorm[row];
                    v0 += xn * s_u[col];
                    v1 += xn * s_u[col + 1];
                }
                if (EPI == 1) { v0 = tanhf(v0); v1 = tanhf(v1); }
                if (WF32) *(float2*)(Cf + off) = make_float2(v0, v1);
                if (WH16) {
                    __half2 p;
                    p.x = __float2half(v0);
                    p.y = __float2half(v1);
                    *(__half2*)(Ch + off) = p;
                }
            }
        }
    }
}

// ---------------- FFMA SGEMM (fp32-exact) --------------------------------------------
#define BM 128
#define BN 128
#define BK 8

template <int EPI, int WC, int DCOUT>   // EPI 0:+bias 1:tanh 2:dist (DCOUT: write centered fp16)
__global__ void __launch_bounds__(256)
sgemm_kernel(const float* __restrict__ A, const float* __restrict__ B,
             const float* __restrict__ bias, const float* __restrict__ rown,
             float* __restrict__ C, __half* __restrict__ Dc,
             int K, int ldb, int ldc) {
    __shared__ __align__(16) float As[2][BK][BM];
    __shared__ __align__(16) float Bs[2][BK][BN];
    const int tid = threadIdx.x;
    const int tx = tid & 15, ty = tid >> 4;
    const int m0 = blockIdx.y * BM, n0 = blockIdx.x * BN;
    const int arow = tid >> 1, akq = (tid & 1) * 4;
    const float* Aptr = A + (size_t)(m0 + arow) * K + akq;
    const int brow = tid >> 5, bcol = (tid & 31) * 4;
    const float* Bptr = B + (size_t)brow * ldb + n0 + bcol;
    float acc[8][8];
#pragma unroll
    for (int i = 0; i < 8; i++)
#pragma unroll
        for (int j = 0; j < 8; j++) acc[i][j] = 0.f;
    const int nt = K / BK;
    float4 a4 = *(const float4*)(Aptr);
    float4 b4 = *(const float4*)(Bptr);
    As[0][akq + 0][arow] = a4.x; As[0][akq + 1][arow] = a4.y;
    As[0][akq + 2][arow] = a4.z; As[0][akq + 3][arow] = a4.w;
    *(float4*)&Bs[0][brow][bcol] = b4;
    __syncthreads();
    int cur = 0;
    for (int t = 0; t < nt; t++) {
        if (t + 1 < nt) {
            a4 = *(const float4*)(Aptr + (t + 1) * BK);
            b4 = *(const float4*)(Bptr + (size_t)(t + 1) * BK * ldb);
        }
#pragma unroll
        for (int kk = 0; kk < BK; kk++) {
            float4 a0 = *(const float4*)&As[cur][kk][ty * 4];
            float4 a1 = *(const float4*)&As[cur][kk][64 + ty * 4];
            float4 b0 = *(const float4*)&Bs[cur][kk][tx * 4];
            float4 b1 = *(const float4*)&Bs[cur][kk][64 + tx * 4];
            float ar[8] = {a0.x, a0.y, a0.z, a0.w, a1.x, a1.y, a1.z, a1.w};
            float br[8] = {b0.x, b0.y, b0.z, b0.w, b1.x, b1.y, b1.z, b1.w};
#pragma unroll
            for (int i = 0; i < 8; i++)
#pragma unroll
                for (int j = 0; j < 8; j++) acc[i][j] = fmaf(ar[i], br[j], acc[i][j]);
        }
        if (t + 1 < nt) {
            int nx = cur ^ 1;
            As[nx][akq + 0][arow] = a4.x; As[nx][akq + 1][arow] = a4.y;
            As[nx][akq + 2][arow] = a4.z; As[nx][akq + 3][arow] = a4.w;
            *(float4*)&Bs[nx][brow][bcol] = b4;
        }
        __syncthreads();
        cur ^= 1;
    }
#pragma unroll
    for (int i = 0; i < 8; i++) {
        int r = m0 + ((i < 4) ? (ty * 4 + i) : (64 + ty * 4 + (i - 4)));
        float rn = (EPI == 2) ? rown[r] : 0.f;
#pragma unroll
        for (int jh = 0; jh < 2; jh++) {
            int c = n0 + jh * 64 + tx * 4;
            float4 bv = *(const float4*)(bias + c);
            const float* ap = &acc[i][jh * 4];
            float4 v;
            if (EPI == 2) {
                // IMPORTANT: identical association to the R14-passing kernel
                // (rn + bv) - 2*ap  -> feeds g_dist / argmin (bit-exact)
                v.x = rn + bv.x - 2.f * ap[0];
                v.y = rn + bv.y - 2.f * ap[1];
                v.z = rn + bv.z - 2.f * ap[2];
                v.w = rn + bv.w - 2.f * ap[3];
                if (DCOUT) {
                    // centered d' = bv - 2*ap (small, fp16-safe) -> feeds the actor
                    float c0 = bv.x - 2.f * ap[0];
                    float c1 = bv.y - 2.f * ap[1];
                    float c2 = bv.z - 2.f * ap[2];
                    float c3 = bv.w - 2.f * ap[3];
                    __half2 p0, p1;
                    p0.x = __float2half(c0); p0.y = __float2half(c1);
                    p1.x = __float2half(c2); p1.y = __float2half(c3);
                    size_t off = (size_t)r * ldc + c;
                    *(__half2*)(Dc + off) = p0;
                    *(__half2*)(Dc + off + 2) = p1;
                }
            } else {
                v.x = ap[0] + bv.x; v.y = ap[1] + bv.y;
                v.z = ap[2] + bv.z; v.w = ap[3] + bv.w;
                if (EPI == 1) {
                    v.x = tanhf(v.x); v.y = tanhf(v.y);
                    v.z = tanhf(v.z); v.w = tanhf(v.w);
                }
            }
            if (WC) *(float4*)(C + (size_t)r * ldc + c) = v;
        }
    }
}

// ---------------- small kernels --------------------------------------------------------
__global__ void prep_codebook_kernel(const float* __restrict__ cb) {
    int k = blockIdx.x;
    float s = 0.f;
    for (int d = threadIdx.x; d < OBS; d += blockDim.x) {
        float v = cb[(size_t)k * OBS + d];
        g_cbT[(size_t)d * KCB + k] = v;
        s += v * v;
    }
    s = blockReduceSum(s);
    if (threadIdx.x == 0) g_cnorm[k] = s;
}

__global__ void rownorm_kernel(const float* __restrict__ x) {
    int b = blockIdx.x;
    const float* r = x + (size_t)b * OBS;
    float s = 0.f;
    for (int d = threadIdx.x; d < OBS; d += blockDim.x) {
        float v = r[d];
        s += v * v;
    }
    s = blockReduceSum(s);
    if (threadIdx.x == 0) g_xnorm[b] = s;
}

// u1[j] = sum_k act_w1[(1024+k)*2048 + j], k in [0,512)
__global__ void colsum_kernel(const float* __restrict__ W1) {
    int j = blockIdx.x * blockDim.x + threadIdx.x;  // 2048 total
    float s = 0.f;
    for (int k = 0; k < 512; ++k) s += W1[(size_t)(1024 + k) * 2048 + j];
    g_u1[j] = s;
}

__global__ void argmin_kernel(const float* __restrict__ dist, float* __restrict__ prop_out_f) {
    __shared__ float sv[256];
    __shared__ int si[256];
    int b = blockIdx.x;
    const float* r = dist + (size_t)b * KCB;
    float best = INFINITY;
    int bi = KCB;
    for (int k = threadIdx.x; k < KCB; k += 256) {
        float v = r[k];
        if (v < best) { best = v; bi = k; }
    }
    sv[threadIdx.x] = best;
    si[threadIdx.x] = bi;
    __syncthreads();
    for (int s = 128; s > 0; s >>= 1) {
        if (threadIdx.x < s) {
            float ov = sv[threadIdx.x + s];
            int oi = si[threadIdx.x + s];
            if (ov < sv[threadIdx.x] || (ov == sv[threadIdx.x] && oi < si[threadIdx.x])) {
                sv[threadIdx.x] = ov;
                si[threadIdx.x] = oi;
            }
        }
        __syncthreads();
    }
    if (threadIdx.x == 0) {
        g_prop[b] = si[0];
        prop_out_f[b] = (float)si[0];
    }
}

__global__ void xhalf_kernel(const float* __restrict__ X, __half* __restrict__ xh) {
    size_t i = (size_t)blockIdx.x * blockDim.x + threadIdx.x;
    xh[i] = __float2half(X[i]);
}

// transpose to fp16: W[K,N] f32 -> [N,K] fp16
__global__ void whalf_kernel(const float* __restrict__ W, __half* __restrict__ hv, int K, int N) {
    __shared__ float t[32][33];
    const int n0 = blockIdx.x * 32, k0 = blockIdx.y * 32;
    const int tx = threadIdx.x, ty = threadIdx.y;
#pragma unroll
    for (int i = 0; i < 4; i++)
        t[ty + i * 8][tx] = W[(size_t)(k0 + ty + i * 8) * N + n0 + tx];
    __syncthreads();
#pragma unroll
    for (int i = 0; i < 4; i++) {
        int n = ty + i * 8;
        hv[(size_t)(n0 + n) * K + k0 + tx] = __float2half(t[tx][n]);
    }
}

__global__ void loss_partial_kernel(const float* __restrict__ dx, const float* __restrict__ cb) {
    const size_t NTOT = (size_t)BSZ * OBS;
    float s1 = 0.f, s2 = 0.f;
    for (size_t i = (size_t)blockIdx.x * blockDim.x + threadIdx.x; i < NTOT;
         i += (size_t)gridDim.x * blockDim.x) {
        int b = (int)(i >> 10);
        int d = (int)(i & 1023);
        size_t ko = (size_t)g_prop[b] * OBS + d;
        float a = dx[i] - g_cb_recon[ko];
        s1 += a * a;
        float c = g_enc[i] - cb[ko];
        s2 += c * c;
    }
    s1 = blockReduceSum(s1);
    __syncthreads();
    s2 = blockReduceSum(s2);
    if (threadIdx.x == 0) {
        g_part[2 * blockIdx.x + 0] = s1;
        g_part[2 * blockIdx.x + 1] = s2;
    }
}

__global__ void finalize_total_kernel(int nb, float* __restrict__ out_total) {
    float s1 = 0.f, s2 = 0.f;
    for (int i = threadIdx.x; i < nb; i += 256) {
        s1 += g_part[2 * i + 0];
        s2 += g_part[2 * i + 1];
    }
    s1 = blockReduceSum(s1);
    __syncthreads();
    s2 = blockReduceSum(s2);
    if (threadIdx.x == 0) {
        const float inv = 1.f / ((float)BSZ * (float)OBS);
        float tot = s1 * inv + 2.f * (s2 * inv);
        g_total[0] = tot;
        out_total[0] = tot;
    }
}

__global__ void policy_kernel(const float* __restrict__ A_, const float* __restrict__ log_std,
                              float* __restrict__ out_loss, float* __restrict__ out_losspi) {
    int b = blockIdx.x;
    int j = threadIdx.x;
    float ls = log_std[j];
    float sd = expf(ls);
    float z = (A_[(size_t)b * OUTD + j] - g_mu[(size_t)b * OUTD + j]) / sd;
    float logp = -0.5f * z * z - ls - 0.5f * LOG2PI_F;
    float term = 1.f / (expf(logp) + 0.1f);
    float lp = blockReduceSum(term);
    if (threadIdx.x == 0) {
        out_losspi[b] = lp;
        out_loss[b] = lp * g_total[0];
    }
}

// ---------------- launch ----------------------------------------------------------------
extern "C" void kernel_launch(void* const* d_in, const int* in_sizes, int n_in,
                              void* d_out, int out_size) {
    const float* X        = (const float*)d_in[0];
    const float* Delta_X  = (const float*)d_in[1];
    const float* A        = (const float*)d_in[2];
    const float* enc_w1   = (const float*)d_in[3];
    const float* enc_b1   = (const float*)d_in[4];
    const float* enc_w2   = (const float*)d_in[5];
    const float* enc_b2   = (const float*)d_in[6];
    const float* prenet_w = (const float*)d_in[7];
    const float* prenet_b = (const float*)d_in[8];
    const float* codebook = (const float*)d_in[9];
    const float* postnet_w= (const float*)d_in[10];
    const float* postnet_b= (const float*)d_in[11];
    const float* dec_w1   = (const float*)d_in[12];
    const float* dec_b1   = (const float*)d_in[13];
    const float* dec_w2   = (const float*)d_in[14];
    const float* dec_b2   = (const float*)d_in[15];
    const float* dec_w3   = (const float*)d_in[16];
    const float* dec_b3   = (const float*)d_in[17];
    const float* act_w1   = (const float*)d_in[18];
    const float* act_b1   = (const float*)d_in[19];
    const float* act_w2   = (const float*)d_in[20];
    const float* act_b2   = (const float*)d_in[21];
    const float* act_w3   = (const float*)d_in[22];
    const float* act_b3   = (const float*)d_in[23];
    const float* log_std  = (const float*)d_in[24];

    float* out = (float*)d_out;
    float* out_loss   = out;
    float* out_losspi = out + BSZ;
    float* out_X      = out + 2 * (size_t)BSZ;
    float* out_prop   = out + 2 * (size_t)BSZ + (size_t)BSZ * OBS;
    float* out_total  = out_prop + BSZ;

    float *p_h1, *p_h2, *p_enc, *p_dist, *p_mu, *p_cbT, *p_cnorm, *p_xnorm;
    float *p_d0, *p_d1, *p_d2, *p_rec;
    __half *p_wt, *p_xh, *p_dc, *p_a1, *p_a2;
    cudaGetSymbolAddress((void**)&p_h1, g_h1);
    cudaGetSymbolAddress((void**)&p_h2, g_h2);
    cudaGetSymbolAddress((void**)&p_enc, g_enc);
    cudaGetSymbolAddress((void**)&p_dist, g_dist);
    cudaGetSymbolAddress((void**)&p_mu, g_mu);
    cudaGetSymbolAddress((void**)&p_cbT, g_cbT);
    cudaGetSymbolAddress((void**)&p_cnorm, g_cnorm);
    cudaGetSymbolAddress((void**)&p_xnorm, g_xnorm);
    cudaGetSymbolAddress((void**)&p_d0, g_cb_d0);
    cudaGetSymbolAddress((void**)&p_d1, g_cb_d1);
    cudaGetSymbolAddress((void**)&p_d2, g_cb_d2);
    cudaGetSymbolAddress((void**)&p_rec, g_cb_recon);
    cudaGetSymbolAddress((void**)&p_wt, g_wt);
    cudaGetSymbolAddress((void**)&p_xh, g_xs);
    cudaGetSymbolAddress((void**)&p_dc, g_dc);
    cudaGetSymbolAddress((void**)&p_a1, g_a1);
    cudaGetSymbolAddress((void**)&p_a2, g_a2);

    cudaFuncSetAttribute(mma1_gemm<1, 0, 1, 1, 1>, cudaFuncAttributeMaxDynamicSharedMemorySize, MMA1_SMEM);
    cudaFuncSetAttribute(mma1_gemm<1, 0, 1, 0, 0>, cudaFuncAttributeMaxDynamicSharedMemorySize, MMA1_SMEM);
    cudaFuncSetAttribute(mma1_gemm<0, 1, 0, 0, 0>, cudaFuncAttributeMaxDynamicSharedMemorySize, MMA1_SMEM);

    static cudaStream_t s2 = nullptr;
    static cudaEvent_t evRoot = nullptr, evW = nullptr, evArg = nullptr, evTot = nullptr;
    if (s2 == nullptr) {
        cudaStreamCreateWithFlags(&s2, cudaStreamNonBlocking);
        cudaEventCreateWithFlags(&evRoot, cudaEventDisableTiming);
        cudaEventCreateWithFlags(&evW, cudaEventDisableTiming);
        cudaEventCreateWithFlags(&evArg, cudaEventDisableTiming);
        cudaEventCreateWithFlags(&evTot, cudaEventDisableTiming);
    }

    dim3 tb(32, 8);

    cudaEventRecord(evRoot, 0);
    cudaStreamWaitEvent(s2, evRoot, 0);

    // ---------- s2 (block A): conversions, decoder-512, out_X ----------
    xhalf_kernel<<<(BSZ * OBS) / 256, 256, 0, s2>>>(X, p_xh);
    whalf_kernel<<<dim3(2048 / 32, 1536 / 32), tb, 0, s2>>>(act_w1, p_wt + O_W1, 1536, 2048);
    whalf_kernel<<<dim3(2048 / 32, 2048 / 32), tb, 0, s2>>>(act_w2, p_wt + O_W2, 2048, 2048);
    whalf_kernel<<<dim3(256 / 32, 2048 / 32), tb, 0, s2>>>(act_w3, p_wt + O_A3, 2048, 256);
    colsum_kernel<<<2048 / 256, 256, 0, s2>>>(act_w1);
    cudaEventRecord(evW, s2);
    sgemm_kernel<1, 1, 0><<<dim3(1024 / BN, KCB / BM), 256, 0, s2>>>(codebook, postnet_w, postnet_b, nullptr, p_d0, nullptr, 1024, 1024, 1024);
    sgemm_kernel<1, 1, 0><<<dim3(2048 / BN, KCB / BM), 256, 0, s2>>>(p_d0, dec_w1, dec_b1, nullptr, p_d1, nullptr, 1024, 2048, 2048);
    sgemm_kernel<1, 1, 0><<<dim3(2048 / BN, KCB / BM), 256, 0, s2>>>(p_d1, dec_w2, dec_b2, nullptr, p_d2, nullptr, 2048, 2048, 2048);
    sgemm_kernel<0, 1, 0><<<dim3(1024 / BN, KCB / BM), 256, 0, s2>>>(p_d2, dec_w3, dec_b3, nullptr, p_rec, nullptr, 2048, 1024, 1024);
    cudaMemcpyAsync(out_X, X, (size_t)BSZ * OBS * sizeof(float), cudaMemcpyDeviceToDevice, s2);

    // ---------- main: encoder (fp32) + distances (bit-identical) + argmin ----------
    prep_codebook_kernel<<<KCB, 256>>>(codebook);
    sgemm_kernel<1, 1, 0><<<dim3(512 / BN, BSZ / BM), 256>>>(Delta_X, enc_w1, enc_b1, nullptr, p_h1, nullptr, 1024, 512, 512);
    sgemm_kernel<1, 1, 0><<<dim3(1024 / BN, BSZ / BM), 256>>>(p_h1, enc_w2, enc_b2, nullptr, p_h2, nullptr, 512, 1024, 1024);
    sgemm_kernel<0, 1, 0><<<dim3(1024 / BN, BSZ / BM), 256>>>(p_h2, prenet_w, prenet_b, nullptr, p_enc, nullptr, 1024, 1024, 1024);
    rownorm_kernel<<<BSZ, 256>>>(p_enc);
    sgemm_kernel<2, 1, 1><<<dim3(KCB / BN, BSZ / BM), 256>>>(p_enc, p_cbT, p_cnorm, p_xnorm, p_dist, p_dc, OBS, KCB, KCB);
    argmin_kernel<<<BSZ, 256>>>(p_dist, out_prop);
    cudaEventRecord(evArg, 0);

    // ---------- s2 (block B): VQ losses ----------
    cudaStreamWaitEvent(s2, evArg, 0);
    loss_partial_kernel<<<2048, 256, 0, s2>>>(Delta_X, codebook);
    finalize_total_kernel<<<1, 256, 0, s2>>>(2048, out_total);
    cudaEventRecord(evTot, s2);

    // ---------- main: actor (single-product fp16 tensor cores) ----------
    cudaStreamWaitEvent(0, evW, 0);
    // act1: a1 = tanh([X | d'] @ W1 + xnorm*u1 + b1), K=1536 fused
    mma1_gemm<1, 0, 1, 1, 1><<<dim3(16, 256), 256, MMA1_SMEM>>>(
        p_xh, p_dc, 1024, p_wt + O_W1, 1536, act_b1, nullptr, p_a1, 2048, 1536);
    // act2: a2 = tanh(a1 @ W2 + b2)
    mma1_gemm<1, 0, 1, 0, 0><<<dim3(16, 256), 256, MMA1_SMEM>>>(
        p_a1, nullptr, 2048, p_wt + O_W2, 2048, act_b2, nullptr, p_a2, 2048, 2048);
    // act3: mu = a2 @ W3 + b3
    mma1_gemm<0, 1, 0, 0, 0><<<dim3(2, 256), 256, MMA1_SMEM>>>(
        p_a2, nullptr, 2048, p_wt + O_A3, 2048, act_b3, p_mu, nullptr, 256, 2048);

    cudaStreamWaitEvent(0, evTot, 0);
    policy_kernel<<<BSZ, 256>>>(A, log_std, out_loss, out_losspi);
}